// round 2
// baseline (speedup 1.0000x reference)
#include <cuda_runtime.h>
#include <math.h>

#define DIMC 256
#define NTOK 128
#define BAT  8
#define HID  1024
#define EPSV 1e-5f
#define SAS  258   // sAttn row stride (floats) -- %4==2 to dodge 8-row bank conflicts
#define SATS 17    // sAt row stride

// -------- device scratch (no allocs allowed) --------
__device__ float g_x1 [BAT*NTOK*DIMC];
__device__ float g_q  [BAT*NTOK*DIMC];
__device__ float g_k  [BAT*NTOK*DIMC];
__device__ float g_v  [BAT*NTOK*DIMC];
__device__ float g_agg[BAT*NTOK*DIMC];
__device__ float g_h  [(size_t)BAT*NTOK*NTOK*HID];   // 512 MB hidden scratch

// ======================= Kernel 1: LN1 + q/k/v =======================
__global__ __launch_bounds__(256) void node_pre_kernel(
    const float* __restrict__ x,
    const float* __restrict__ Wq, const float* __restrict__ bq,
    const float* __restrict__ Wk, const float* __restrict__ bk,
    const float* __restrict__ Wv, const float* __restrict__ bv,
    const float* __restrict__ ln1s, const float* __restrict__ ln1b)
{
    __shared__ float sx[4][DIMC];
    int tid = threadIdx.x;
    int row0 = blockIdx.x * 4;
    int w = tid >> 5, lane = tid & 31;
    if (w < 4) {
        const float* xr = x + (size_t)(row0 + w) * DIMC;
        float vals[8], s = 0.f, sq = 0.f;
        #pragma unroll
        for (int u = 0; u < 8; u++) { vals[u] = xr[lane + u*32]; s += vals[u]; sq += vals[u]*vals[u]; }
        #pragma unroll
        for (int o = 16; o > 0; o >>= 1) { s += __shfl_xor_sync(~0u, s, o); sq += __shfl_xor_sync(~0u, sq, o); }
        float mean = s * (1.f/DIMC);
        float rstd = rsqrtf(sq * (1.f/DIMC) - mean*mean + EPSV);
        #pragma unroll
        for (int u = 0; u < 8; u++) {
            int c = lane + u*32;
            float v = (vals[u] - mean) * rstd * ln1s[c] + ln1b[c];
            sx[w][c] = v;
            g_x1[(row0 + w)*DIMC + c] = v;
        }
    }
    __syncthreads();
    int c = tid;
    float aq[4] = {}, ak[4] = {}, av[4] = {};
    for (int k = 0; k < DIMC; k++) {
        float wq = Wq[k*DIMC + c], wk = Wk[k*DIMC + c], wv = Wv[k*DIMC + c];
        #pragma unroll
        for (int r = 0; r < 4; r++) {
            float xv = sx[r][k];
            aq[r] += xv*wq; ak[r] += xv*wk; av[r] += xv*wv;
        }
    }
    #pragma unroll
    for (int r = 0; r < 4; r++) {
        g_q[(row0+r)*DIMC + c] = aq[r] + bq[c];
        g_k[(row0+r)*DIMC + c] = ak[r] + bk[c];
        g_v[(row0+r)*DIMC + c] = av[r] + bv[c];
    }
}

// ======================= GEMM micro-helpers =======================
__device__ __forceinline__ void stage_A16(float* sAt, const float* __restrict__ src,
                                          int lds, int kbase, int tid)
{
    #pragma unroll
    for (int it = 0; it < 8; it++) {
        int l = tid + it*256;
        int j = l >> 4, kk = l & 15;
        sAt[j*SATS + kk] = src[(size_t)j*lds + kbase + kk];
    }
}
__device__ __forceinline__ void stage_B16(float* sBt, const float* __restrict__ W,
                                          int ldw, int kbase, int cbase, int tid)
{
    #pragma unroll
    for (int it = 0; it < 8; it++) {
        int l = tid + it*256;
        int kk = l >> 7, cc = l & 127;
        sBt[kk*NTOK + cc] = W[(size_t)(kbase + kk)*ldw + cbase + cc];
    }
}
__device__ __forceinline__ void fma_At(const float* sAt, const float* sBt,
                                       int r0, int c0, float acc[8][8])
{
    #pragma unroll
    for (int kk = 0; kk < 16; kk++) {
        float a[8], bb[8];
        #pragma unroll
        for (int u = 0; u < 8; u++) a[u] = sAt[(r0+u)*SATS + kk];
        #pragma unroll
        for (int v = 0; v < 8; v++) bb[v] = sBt[kk*NTOK + c0 + v];
        #pragma unroll
        for (int u = 0; u < 8; u++)
            #pragma unroll
            for (int v = 0; v < 8; v++) acc[u][v] += a[u]*bb[v];
    }
}
__device__ __forceinline__ void fma_Attn(const float* sAttn, const float* sBt,
                                         int r0, int c0, int kbase, float acc[8][8])
{
    #pragma unroll
    for (int kk = 0; kk < 16; kk++) {
        float a[8], bb[8];
        #pragma unroll
        for (int u = 0; u < 8; u++) a[u] = sAttn[(r0+u)*SAS + kbase + kk];
        #pragma unroll
        for (int v = 0; v < 8; v++) bb[v] = sBt[kk*NTOK + c0 + v];
        #pragma unroll
        for (int u = 0; u < 8; u++)
            #pragma unroll
            for (int v = 0; v < 8; v++) acc[u][v] += a[u]*bb[v];
    }
}
#define ZERO_ACC(acc) { _Pragma("unroll") for (int u=0;u<8;u++) _Pragma("unroll") for (int v=0;v<8;v++) acc[u][v]=0.f; }

// ======================= Kernel 2: edge mega-kernel =======================
__global__ __launch_bounds__(256, 1) void edge_kernel(
    const float* __restrict__ y,
    const float* __restrict__ We,  const float* __restrict__ be,
    const float* __restrict__ Woe, const float* __restrict__ boe,
    const float* __restrict__ w1,  const float* __restrict__ b1,
    const float* __restrict__ w2,  const float* __restrict__ b2,
    const float* __restrict__ ln4s, const float* __restrict__ ln4b,
    const float* __restrict__ ln6s, const float* __restrict__ ln6b,
    float* __restrict__ yout)
{
    extern __shared__ float sm[];
    float* sAttn = sm;                        // 128 * SAS
    float* sTmp  = sAttn + NTOK*SAS;          // 128 * 128
    float* sAt   = sTmp  + NTOK*NTOK;         // 128 * SATS
    float* sBt   = sAt   + NTOK*SATS;         // 16 * 128
    float* sQ    = sBt   + 16*NTOK;           // 256

    int tid = threadIdx.x;
    int bi  = blockIdx.x;
    int b   = bi >> 7;
    int tx = tid & 15, ty = tid >> 4;
    int r0 = ty * 8, c0 = tx * 8;

    const float* yblk = y + (size_t)bi * NTOK * DIMC;
    size_t hbase = (size_t)bi * NTOK * HID;

    sQ[tid] = g_q[bi*DIMC + tid];

    float acc[8][8];

    // ---- GEMM1: e = y @ We + be ; attn = q*k/sqrt(dk)*(e+1)*e -> sAttn ----
    for (int ct = 0; ct < 2; ct++) {
        ZERO_ACC(acc);
        for (int kt = 0; kt < DIMC/16; kt++) {
            __syncthreads();
            stage_A16(sAt, yblk, DIMC, kt*16, tid);
            stage_B16(sBt, We, DIMC, kt*16, ct*128, tid);
            __syncthreads();
            fma_At(sAt, sBt, r0, c0, acc);
        }
        #pragma unroll
        for (int u = 0; u < 8; u++) {
            int j = r0 + u;
            #pragma unroll
            for (int v = 0; v < 8; v++) {
                int c = ct*128 + c0 + v;
                float e = acc[u][v] + be[c];
                float kv = g_k[(b*NTOK + j)*DIMC + c];
                sAttn[j*SAS + c] = sQ[c]*kv*0.17677669529663687f * (e + 1.f) * e;
            }
        }
    }
    __syncthreads();

    // ---- softmax over j (CTA-local) + agg = sum_j p*v ----
    {
        int c = tid;
        float m = -1e30f;
        for (int j = 0; j < NTOK; j++) m = fmaxf(m, sAttn[j*SAS + c]);
        float s = 0.f, aggv = 0.f;
        for (int j = 0; j < NTOK; j++) {
            float p = __expf(sAttn[j*SAS + c] - m);
            s += p;
            aggv += p * g_v[(b*NTOK + j)*DIMC + c];
        }
        g_agg[bi*DIMC + c] = aggv / s;
    }

    // ---- GEMM2: edge_out = attn @ Woe + boe ; + y residual ----
    for (int ct = 0; ct < 2; ct++) {
        ZERO_ACC(acc);
        for (int kt = 0; kt < DIMC/16; kt++) {
            __syncthreads();
            stage_B16(sBt, Woe, DIMC, kt*16, ct*128, tid);
            __syncthreads();
            fma_Attn(sAttn, sBt, r0, c0, kt*16, acc);
        }
        __syncthreads();  // all reads of sAttn done before overwriting (ct==1)
        #pragma unroll
        for (int u = 0; u < 8; u++) {
            int j = r0 + u;
            #pragma unroll
            for (int v = 0; v < 8; v++) {
                int c = ct*128 + c0 + v;
                float val = acc[u][v] + boe[c] + yblk[(size_t)j*DIMC + c];
                if (ct == 0) sTmp[j*NTOK + c0 + v] = val;
                else         sAttn[j*SAS + c] = val;
            }
        }
    }
    __syncthreads();
    for (int l = tid; l < NTOK*NTOK; l += 256) {
        int j = l >> 7, c = l & 127;
        sAttn[j*SAS + c] = sTmp[l];
    }
    __syncthreads();

    // ---- LN4 -> y2 (in place in sAttn) ----
    {
        int w = tid >> 5, lane = tid & 31;
        for (int j = w; j < NTOK; j += 8) {
            float s = 0.f, sq = 0.f;
            #pragma unroll
            for (int u = 0; u < 8; u++) {
                float v = sAttn[j*SAS + lane + u*32];
                s += v; sq += v*v;
            }
            #pragma unroll
            for (int o = 16; o > 0; o >>= 1) { s += __shfl_xor_sync(~0u,s,o); sq += __shfl_xor_sync(~0u,sq,o); }
            float mean = s * (1.f/256.f);
            float rstd = rsqrtf(sq*(1.f/256.f) - mean*mean + EPSV);
            #pragma unroll
            for (int u = 0; u < 8; u++) {
                int c = lane + u*32;
                float v = sAttn[j*SAS + c];
                sAttn[j*SAS + c] = (v - mean)*rstd*ln4s[c] + ln4b[c];
            }
        }
    }
    __syncthreads();

    // ---- GEMM3: h = relu(y2 @ w1 + b1) -> g_h ----
    for (int ht = 0; ht < HID/128; ht++) {
        ZERO_ACC(acc);
        for (int kt = 0; kt < DIMC/16; kt++) {
            __syncthreads();
            stage_B16(sBt, w1, HID, kt*16, ht*128, tid);
            __syncthreads();
            fma_Attn(sAttn, sBt, r0, c0, kt*16, acc);
        }
        #pragma unroll
        for (int u = 0; u < 8; u++) {
            int j = r0 + u;
            #pragma unroll
            for (int v = 0; v < 8; v++) {
                int hc = ht*128 + c0 + v;
                g_h[hbase + (size_t)j*HID + hc] = fmaxf(acc[u][v] + b1[hc], 0.f);
            }
        }
    }

    // ---- GEMM4: mlp = h @ w2 + b2 ; + y2 ; in place in sAttn ----
    for (int ct = 0; ct < 2; ct++) {
        ZERO_ACC(acc);
        for (int kt = 0; kt < HID/16; kt++) {
            __syncthreads();
            stage_A16(sAt, g_h + hbase, HID, kt*16, tid);
            stage_B16(sBt, w2, DIMC, kt*16, ct*128, tid);
            __syncthreads();
            fma_At(sAt, sBt, r0, c0, acc);
        }
        #pragma unroll
        for (int u = 0; u < 8; u++) {
            int j = r0 + u;
            #pragma unroll
            for (int v = 0; v < 8; v++) {
                int c = ct*128 + c0 + v;
                sAttn[j*SAS + c] = acc[u][v] + b2[c] + sAttn[j*SAS + c];
            }
        }
    }
    __syncthreads();

    // ---- LN6 -> y_out ----
    {
        int w = tid >> 5, lane = tid & 31;
        float* outblk = yout + (size_t)bi * NTOK * DIMC;
        for (int j = w; j < NTOK; j += 8) {
            float s = 0.f, sq = 0.f;
            #pragma unroll
            for (int u = 0; u < 8; u++) {
                float v = sAttn[j*SAS + lane + u*32];
                s += v; sq += v*v;
            }
            #pragma unroll
            for (int o = 16; o > 0; o >>= 1) { s += __shfl_xor_sync(~0u,s,o); sq += __shfl_xor_sync(~0u,sq,o); }
            float mean = s * (1.f/256.f);
            float rstd = rsqrtf(sq*(1.f/256.f) - mean*mean + EPSV);
            #pragma unroll
            for (int u = 0; u < 8; u++) {
                int c = lane + u*32;
                float v = sAttn[j*SAS + c];
                outblk[(size_t)j*DIMC + c] = (v - mean)*rstd*ln6s[c] + ln6b[c];
            }
        }
    }
}

// ======================= Kernel 3: node path finish =======================
__global__ __launch_bounds__(256) void node_post_kernel(
    const float* __restrict__ Won, const float* __restrict__ bon,
    const float* __restrict__ w1,  const float* __restrict__ b1,
    const float* __restrict__ w2,  const float* __restrict__ b2,
    const float* __restrict__ ln3s, const float* __restrict__ ln3b,
    const float* __restrict__ ln5s, const float* __restrict__ ln5b,
    float* __restrict__ xout)
{
    __shared__ float sx2[8][DIMC];
    __shared__ float sh[8][HID];
    int tid = threadIdx.x;
    int row0 = blockIdx.x * 8;
    int c = tid;

    // node_out = agg @ Won + bon ; +x1 residual
    {
        float acc[8] = {};
        for (int k = 0; k < DIMC; k++) {
            float wv = Won[k*DIMC + c];
            #pragma unroll
            for (int r = 0; r < 8; r++) acc[r] += g_agg[(row0+r)*DIMC + k] * wv;
        }
        #pragma unroll
        for (int r = 0; r < 8; r++)
            sx2[r][c] = acc[r] + bon[c] + g_x1[(row0+r)*DIMC + c];
    }
    __syncthreads();
    // LN3 in place (warp per row)
    {
        int w = tid >> 5, lane = tid & 31;
        float s = 0.f, sq = 0.f;
        #pragma unroll
        for (int u = 0; u < 8; u++) { float v = sx2[w][lane+u*32]; s += v; sq += v*v; }
        #pragma unroll
        for (int o = 16; o > 0; o >>= 1) { s += __shfl_xor_sync(~0u,s,o); sq += __shfl_xor_sync(~0u,sq,o); }
        float mean = s * (1.f/256.f);
        float rstd = rsqrtf(sq*(1.f/256.f) - mean*mean + EPSV);
        #pragma unroll
        for (int u = 0; u < 8; u++) {
            int cc = lane + u*32;
            sx2[w][cc] = (sx2[w][cc] - mean)*rstd*ln3s[cc] + ln3b[cc];
        }
    }
    __syncthreads();
    // hidden = relu(x2 @ w1 + b1)
    {
        float hacc[8][4] = {};
        for (int k = 0; k < DIMC; k++) {
            float xv[8];
            #pragma unroll
            for (int r = 0; r < 8; r++) xv[r] = sx2[r][k];
            #pragma unroll
            for (int m = 0; m < 4; m++) {
                float wv = w1[(size_t)k*HID + tid + m*256];
                #pragma unroll
                for (int r = 0; r < 8; r++) hacc[r][m] += xv[r]*wv;
            }
        }
        #pragma unroll
        for (int m = 0; m < 4; m++) {
            float bb = b1[tid + m*256];
            #pragma unroll
            for (int r = 0; r < 8; r++) sh[r][tid + m*256] = fmaxf(hacc[r][m] + bb, 0.f);
        }
    }
    __syncthreads();
    // mlp = h @ w2 + b2 ; +x2 residual
    {
        float acc[8] = {};
        for (int k = 0; k < HID; k++) {
            float wv = w2[k*DIMC + c];
            #pragma unroll
            for (int r = 0; r < 8; r++) acc[r] += sh[r][k]*wv;
        }
        __syncthreads();
        #pragma unroll
        for (int r = 0; r < 8; r++)
            sh[r][c] = acc[r] + b2[c] + sx2[r][c];
    }
    __syncthreads();
    // LN5 -> x_out
    {
        int w = tid >> 5, lane = tid & 31;
        float s = 0.f, sq = 0.f;
        #pragma unroll
        for (int u = 0; u < 8; u++) { float v = sh[w][lane+u*32]; s += v; sq += v*v; }
        #pragma unroll
        for (int o = 16; o > 0; o >>= 1) { s += __shfl_xor_sync(~0u,s,o); sq += __shfl_xor_sync(~0u,sq,o); }
        float mean = s * (1.f/256.f);
        float rstd = rsqrtf(sq*(1.f/256.f) - mean*mean + EPSV);
        #pragma unroll
        for (int u = 0; u < 8; u++) {
            int cc = lane + u*32;
            xout[(size_t)(row0+w)*DIMC + cc] = (sh[w][cc] - mean)*rstd*ln5s[cc] + ln5b[cc];
        }
    }
}

// ======================= launch =======================
extern "C" void kernel_launch(void* const* d_in, const int* in_sizes, int n_in,
                              void* d_out, int out_size)
{
    const float* x    = (const float*)d_in[0];
    const float* y    = (const float*)d_in[1];
    const float* Wq   = (const float*)d_in[2];  const float* bq  = (const float*)d_in[3];
    const float* Wk   = (const float*)d_in[4];  const float* bk  = (const float*)d_in[5];
    const float* Wv   = (const float*)d_in[6];  const float* bv  = (const float*)d_in[7];
    const float* We   = (const float*)d_in[8];  const float* be  = (const float*)d_in[9];
    const float* Woe  = (const float*)d_in[10]; const float* boe = (const float*)d_in[11];
    const float* Won  = (const float*)d_in[12]; const float* bon = (const float*)d_in[13];
    const float* m1w1 = (const float*)d_in[14]; const float* m1b1= (const float*)d_in[15];
    const float* m1w2 = (const float*)d_in[16]; const float* m1b2= (const float*)d_in[17];
    const float* m2w1 = (const float*)d_in[18]; const float* m2b1= (const float*)d_in[19];
    const float* m2w2 = (const float*)d_in[20]; const float* m2b2= (const float*)d_in[21];
    const float* ln1s = (const float*)d_in[22]; const float* ln1b= (const float*)d_in[23];
    const float* ln3s = (const float*)d_in[24]; const float* ln3b= (const float*)d_in[25];
    const float* ln4s = (const float*)d_in[26]; const float* ln4b= (const float*)d_in[27];
    const float* ln5s = (const float*)d_in[28]; const float* ln5b= (const float*)d_in[29];
    const float* ln6s = (const float*)d_in[30]; const float* ln6b= (const float*)d_in[31];

    float* out  = (float*)d_out;
    float* xout = out;                               // (8,128,256)
    float* yout = out + BAT*NTOK*DIMC;               // (8,128,128,256)

    int smem = (NTOK*SAS + NTOK*NTOK + NTOK*SATS + 16*NTOK + DIMC) * (int)sizeof(float);
    cudaFuncSetAttribute(edge_kernel, cudaFuncAttributeMaxDynamicSharedMemorySize, smem);

    node_pre_kernel<<<BAT*NTOK/4, 256>>>(x, Wq, bq, Wk, bk, Wv, bv, ln1s, ln1b);
    edge_kernel<<<BAT*NTOK, 256, smem>>>(y, We, be, Woe, boe,
                                         m2w1, m2b1, m2w2, m2b2,
                                         ln4s, ln4b, ln6s, ln6b, yout);
    node_post_kernel<<<BAT*NTOK/8, 256>>>(Won, bon, m1w1, m1b1, m1w2, m1b2,
                                          ln3s, ln3b, ln5s, ln5b, xout);
}

// round 4
// speedup vs baseline: 2.3546x; 2.3546x over previous
#include <cuda_runtime.h>
#include <math.h>
#include <stdint.h>

#define DIMC 256
#define NTOK 128
#define BAT  8
#define HID  1024
#define EPSV 1e-5f
#define ASCALE 0.17677669529663687f

#define LDA 260    // sA row stride (floats): 260 % 32 == 4 -> conflict-free frags
#define LDH 132    // sH row stride
#define LDB1 36    // B chunk stride, 32-wide k chunks
#define LDB2 20    // B chunk stride, 16-wide k chunks

// -------- device scratch --------
__device__ float g_x1 [BAT*NTOK*DIMC];
__device__ float g_q  [BAT*NTOK*DIMC];
__device__ float g_k  [BAT*NTOK*DIMC];
__device__ float g_v  [BAT*NTOK*DIMC];
__device__ float g_agg[BAT*NTOK*DIMC];
__device__ float g_WeT [DIMC*DIMC];   // [n=256][k=256]
__device__ float g_WoeT[DIMC*DIMC];   // [n=256][k=256]
__device__ float g_W1T [HID*DIMC];    // [n=1024][k=256]
__device__ float g_W2T [DIMC*HID];    // [n=256][k=1024]

// -------- helpers --------
__device__ __forceinline__ float rna_tf32(float x){
    uint32_t r;
    asm("cvt.rna.tf32.f32 %0, %1;" : "=r"(r) : "f"(x));
    return __uint_as_float(r);
}
__device__ __forceinline__ void mma8(float* d, const uint32_t* a, const uint32_t* b){
    asm volatile("mma.sync.aligned.m16n8k8.row.col.f32.tf32.tf32.f32 "
        "{%0,%1,%2,%3},{%4,%5,%6,%7},{%8,%9},{%0,%1,%2,%3};"
        : "+f"(d[0]),"+f"(d[1]),"+f"(d[2]),"+f"(d[3])
        : "r"(a[0]),"r"(a[1]),"r"(a[2]),"r"(a[3]),"r"(b[0]),"r"(b[1]));
}

// Generic k-chunked GEMM pass. A resident in smem [128 x K] (lda stride),
// B fetched from global [nrows x ldgb] (n-major, tf32-prepped) in KCH-wide
// k-chunks into sB (LDB stride). Warp computes a 64 x (NF*8) tile at
// (arow0, bn0) of the staged n-window. MF fixed = 4 (64 rows).
template<int NF, int LDB, int KCH>
__device__ __forceinline__ void gemm_run(
    const float* sA, int lda, int arow0,
    const float* __restrict__ gB, int ldgb, int kglob0, int nrows, int nkc,
    float* sB, int bn0, float c[4][NF][4], int tid, int lane)
{
    const int F4 = KCH/4;
    for (int kc = 0; kc < nkc; kc++){
        __syncthreads();
        for (int i = tid; i < nrows*F4; i += 256){
            int n = i / F4, qq = i % F4;
            *(float4*)(sB + n*LDB + qq*4) =
                *(const float4*)(gB + (size_t)n*ldgb + kglob0 + kc*KCH + qq*4);
        }
        __syncthreads();
        #pragma unroll
        for (int ks = 0; ks < KCH/8; ks++){
            int kk = kc*KCH + ks*8;
            uint32_t a[4][4];
            const float* Ab = sA + (size_t)(arow0 + (lane>>2))*lda + kk + (lane&3);
            #pragma unroll
            for (int mf = 0; mf < 4; mf++){
                const float* p = Ab + mf*16*lda;
                a[mf][0] = __float_as_uint(p[0]);
                a[mf][1] = __float_as_uint(p[8*lda]);
                a[mf][2] = __float_as_uint(p[4]);
                a[mf][3] = __float_as_uint(p[8*lda + 4]);
            }
            #pragma unroll
            for (int nf = 0; nf < NF; nf++){
                const float* qp = sB + (size_t)(bn0 + nf*8 + (lane>>2))*LDB + ks*8 + (lane&3);
                uint32_t b[2] = { __float_as_uint(qp[0]), __float_as_uint(qp[4]) };
                #pragma unroll
                for (int mf = 0; mf < 4; mf++) mma8(c[mf][nf], a[mf], b);
            }
        }
    }
}

#define ZERO4(c, NF) { _Pragma("unroll") for (int _m=0;_m<4;_m++) _Pragma("unroll") for (int _n=0;_n<NF;_n++) _Pragma("unroll") for (int _u=0;_u<4;_u++) (c)[_m][_n][_u]=0.f; }

// ================= prep: transpose + tf32-round weights =================
__global__ __launch_bounds__(256) void prep_kernel(
    const float* __restrict__ We, const float* __restrict__ Woe,
    const float* __restrict__ w1, const float* __restrict__ w2)
{
    int idx = blockIdx.x*256 + threadIdx.x;   // 0..262143
    if (idx < DIMC*DIMC){
        int n = idx >> 8, k = idx & 255;
        g_WeT [idx] = rna_tf32(We [k*DIMC + n]);
        g_WoeT[idx] = rna_tf32(Woe[k*DIMC + n]);
    }
    {   // W1T [n=1024][k=256]
        int n = idx >> 8, k = idx & 255;
        g_W1T[idx] = rna_tf32(w1[(size_t)k*HID + n]);
    }
    {   // W2T [n=256][k=1024]
        int n = idx >> 10, k = idx & 1023;
        g_W2T[idx] = rna_tf32(w2[(size_t)k*DIMC + n]);
    }
}

// ================= kernel 1: LN1 + q/k/v =================
__global__ __launch_bounds__(256) void node_pre_kernel(
    const float* __restrict__ x,
    const float* __restrict__ Wq, const float* __restrict__ bq,
    const float* __restrict__ Wk, const float* __restrict__ bk,
    const float* __restrict__ Wv, const float* __restrict__ bv,
    const float* __restrict__ ln1s, const float* __restrict__ ln1b)
{
    __shared__ float sx[4][DIMC];
    int tid = threadIdx.x;
    int row0 = blockIdx.x * 4;
    int w = tid >> 5, lane = tid & 31;
    if (w < 4){
        const float* xr = x + (size_t)(row0 + w) * DIMC;
        float vals[8], s = 0.f, sq = 0.f;
        #pragma unroll
        for (int u = 0; u < 8; u++){ vals[u] = xr[lane + u*32]; s += vals[u]; sq += vals[u]*vals[u]; }
        #pragma unroll
        for (int o = 16; o > 0; o >>= 1){ s += __shfl_xor_sync(~0u,s,o); sq += __shfl_xor_sync(~0u,sq,o); }
        float mean = s * (1.f/DIMC);
        float rstd = rsqrtf(sq*(1.f/DIMC) - mean*mean + EPSV);
        #pragma unroll
        for (int u = 0; u < 8; u++){
            int c = lane + u*32;
            float v = (vals[u]-mean)*rstd*ln1s[c] + ln1b[c];
            sx[w][c] = v;
            g_x1[(row0+w)*DIMC + c] = v;
        }
    }
    __syncthreads();
    int c = tid;
    float aq[4] = {}, ak[4] = {}, av[4] = {};
    for (int k = 0; k < DIMC; k++){
        float wq = Wq[k*DIMC+c], wk = Wk[k*DIMC+c], wv = Wv[k*DIMC+c];
        #pragma unroll
        for (int r = 0; r < 4; r++){
            float xv = sx[r][k];
            aq[r] += xv*wq; ak[r] += xv*wk; av[r] += xv*wv;
        }
    }
    #pragma unroll
    for (int r = 0; r < 4; r++){
        int gr = row0 + r;
        g_q[gr*DIMC + c] = aq[r] + bq[c];
        g_k[gr*DIMC + c] = ak[r] + bk[c];
        g_v[gr*DIMC + c] = av[r] + bv[c];
    }
}

// ================= kernel 2: edge mega-kernel (mma.sync tf32) =================
__global__ __launch_bounds__(256, 1) void edge_kernel(
    const float* __restrict__ y,
    const float* __restrict__ be,  const float* __restrict__ boe,
    const float* __restrict__ b1,  const float* __restrict__ b2,
    const float* __restrict__ ln4s, const float* __restrict__ ln4b,
    const float* __restrict__ ln6s, const float* __restrict__ ln6b,
    float* __restrict__ yout)
{
    extern __shared__ float sm[];
    float* sA   = sm;                 // 128*260 = 33280
    float* sH   = sA + 128*LDA;       // 128*132 = 16896
    float* sB   = sH + 128*LDH;       // 5120
    float* sSum = sB + 5120;          // 256
    float* sSq  = sSum + 256;         // 256
    float* sQ   = sSq + 256;          // 256

    int tid = threadIdx.x, lane = tid & 31, w = tid >> 5;
    int wm = (w >> 2) * 64, wn = w & 3;
    int g = lane >> 2, t = lane & 3;
    int bi = blockIdx.x, b = bi >> 7;
    const float* yblk = y + (size_t)bi * NTOK * DIMC;

    sQ[tid] = g_q[bi*DIMC + tid];
    // stage y -> sA (raw fp32; HMMA truncates to tf32)
    for (int i = tid; i < 128*64; i += 256){
        int r = i >> 6, kq = (i & 63) << 2;
        *(float4*)(sA + r*LDA + kq) = *(const float4*)(yblk + r*DIMC + kq);
    }

    float cE[2][4][4][4];

    // ---- GEMM1: e = y @ We ----
    #pragma unroll
    for (int nc = 0; nc < 2; nc++){
        ZERO4(cE[nc], 4);
        gemm_run<4, LDB1, 32>(sA, LDA, wm, g_WeT + nc*128*DIMC, DIMC, 0, 128, 8,
                              sB, wn*32, cE[nc], tid, lane);
    }
    __syncthreads();
    // epilogue: attn = q*k*scale*(e+1)*e -> sA
    #pragma unroll
    for (int nc = 0; nc < 2; nc++)
    #pragma unroll
    for (int mf = 0; mf < 4; mf++)
    #pragma unroll
    for (int nf = 0; nf < 4; nf++)
    #pragma unroll
    for (int hh = 0; hh < 2; hh++){
        int r = wm + mf*16 + g + hh*8;
        int col = nc*128 + wn*32 + nf*8 + 2*t;
        float e0 = cE[nc][mf][nf][2*hh+0] + be[col];
        float e1 = cE[nc][mf][nf][2*hh+1] + be[col+1];
        const float* kp = g_k + (size_t)(b*NTOK + r)*DIMC + col;
        float v0 = sQ[col]  *kp[0]*ASCALE*(e0 + 1.f)*e0;
        float v1 = sQ[col+1]*kp[1]*ASCALE*(e1 + 1.f)*e1;
        sA[r*LDA + col]     = v0;
        sA[r*LDA + col + 1] = v1;
    }
    __syncthreads();

    // ---- softmax over j + agg ----
    {
        int c = tid;
        float mx = -1e30f;
        for (int j = 0; j < NTOK; j++) mx = fmaxf(mx, sA[j*LDA + c]);
        float s = 0.f, agv = 0.f;
        for (int j = 0; j < NTOK; j++){
            float p = __expf(sA[j*LDA + c] - mx);
            s += p;
            agv += p * g_v[(size_t)(b*NTOK + j)*DIMC + c];
        }
        g_agg[bi*DIMC + c] = agv / s;
    }

    // ---- GEMM2: edge_out = attn @ Woe ----
    #pragma unroll
    for (int nc = 0; nc < 2; nc++){
        ZERO4(cE[nc], 4);
        gemm_run<4, LDB1, 32>(sA, LDA, wm, g_WoeT + nc*128*DIMC, DIMC, 0, 128, 8,
                              sB, wn*32, cE[nc], tid, lane);
    }
    __syncthreads();
    // epilogue: y2_pre = d + boe + y -> sA
    #pragma unroll
    for (int nc = 0; nc < 2; nc++)
    #pragma unroll
    for (int mf = 0; mf < 4; mf++)
    #pragma unroll
    for (int nf = 0; nf < 4; nf++)
    #pragma unroll
    for (int hh = 0; hh < 2; hh++){
        int r = wm + mf*16 + g + hh*8;
        int col = nc*128 + wn*32 + nf*8 + 2*t;
        const float* yp = yblk + (size_t)r*DIMC + col;
        sA[r*LDA + col]     = cE[nc][mf][nf][2*hh+0] + boe[col]   + yp[0];
        sA[r*LDA + col + 1] = cE[nc][mf][nf][2*hh+1] + boe[col+1] + yp[1];
    }
    __syncthreads();

    // ---- LN4 -> y2 (in place) ----
    {
        int ch = tid >> 7, r = tid & 127;
        float* base = sA + r*LDA + ch*128;
        float s = 0.f, sq = 0.f;
        for (int i = 0; i < 128; i++){ float v = base[i]; s += v; sq += v*v; }
        sSum[ch*128 + r] = s; sSq[ch*128 + r] = sq;
        __syncthreads();
        float ss = sSum[r] + sSum[128 + r];
        float sk = sSq[r]  + sSq[128 + r];
        float mean = ss * (1.f/256.f);
        float rstd = rsqrtf(sk*(1.f/256.f) - mean*mean + EPSV);
        for (int i = 0; i < 128; i++){
            int c = ch*128 + i;
            base[i] = (base[i] - mean)*rstd*ln4s[c] + ln4b[c];
        }
    }
    __syncthreads();

    // ---- MLP: GEMM3 (h tiles into sH) interleaved with GEMM4 (accumulate) ----
    float cM[4][8][4];
    ZERO4(cM, 8);
    for (int ht = 0; ht < 8; ht++){
        float cH[4][4][4];
        ZERO4(cH, 4);
        gemm_run<4, LDB1, 32>(sA, LDA, wm, g_W1T + (size_t)ht*128*DIMC, DIMC, 0, 128, 8,
                              sB, wn*32, cH, tid, lane);
        __syncthreads();
        #pragma unroll
        for (int mf = 0; mf < 4; mf++)
        #pragma unroll
        for (int nf = 0; nf < 4; nf++)
        #pragma unroll
        for (int hh = 0; hh < 2; hh++){
            int r = wm + mf*16 + g + hh*8;
            int col = wn*32 + nf*8 + 2*t;
            sH[r*LDH + col]     = fmaxf(cH[mf][nf][2*hh+0] + b1[ht*128 + col],     0.f);
            sH[r*LDH + col + 1] = fmaxf(cH[mf][nf][2*hh+1] + b1[ht*128 + col + 1], 0.f);
        }
        __syncthreads();
        gemm_run<8, LDB2, 16>(sH, LDH, wm, g_W2T, HID, ht*128, 256, 8,
                              sB, wn*64, cM, tid, lane);
    }
    __syncthreads();
    // GEMM4 epilogue: sA = y2 + mlp + b2
    #pragma unroll
    for (int mf = 0; mf < 4; mf++)
    #pragma unroll
    for (int nf = 0; nf < 8; nf++)
    #pragma unroll
    for (int hh = 0; hh < 2; hh++){
        int r = wm + mf*16 + g + hh*8;
        int col = wn*64 + nf*8 + 2*t;
        sA[r*LDA + col]     += cM[mf][nf][2*hh+0] + b2[col];
        sA[r*LDA + col + 1] += cM[mf][nf][2*hh+1] + b2[col+1];
    }
    __syncthreads();

    // ---- LN6 -> yout ----
    {
        int ch = tid >> 7, r = tid & 127;
        float* base = sA + r*LDA + ch*128;
        float s = 0.f, sq = 0.f;
        for (int i = 0; i < 128; i++){ float v = base[i]; s += v; sq += v*v; }
        sSum[ch*128 + r] = s; sSq[ch*128 + r] = sq;
        __syncthreads();
        float ss = sSum[r] + sSum[128 + r];
        float sk = sSq[r]  + sSq[128 + r];
        float mean = ss * (1.f/256.f);
        float rstd = rsqrtf(sk*(1.f/256.f) - mean*mean + EPSV);
        float* op = yout + (size_t)bi*NTOK*DIMC + (size_t)r*DIMC + ch*128;
        for (int i = 0; i < 128; i++){
            int c = ch*128 + i;
            op[i] = (base[i] - mean)*rstd*ln6s[c] + ln6b[c];
        }
    }
}

// ================= kernel 3: node path finish =================
__global__ __launch_bounds__(256) void node_post_kernel(
    const float* __restrict__ Won, const float* __restrict__ bon,
    const float* __restrict__ w1,  const float* __restrict__ b1,
    const float* __restrict__ w2,  const float* __restrict__ b2,
    const float* __restrict__ ln3s, const float* __restrict__ ln3b,
    const float* __restrict__ ln5s, const float* __restrict__ ln5b,
    float* __restrict__ xout)
{
    __shared__ float sx2[8][DIMC];
    __shared__ float sh[8][HID];
    int tid = threadIdx.x;
    int row0 = blockIdx.x * 8;
    int c = tid;
    {
        float acc[8] = {};
        for (int k = 0; k < DIMC; k++){
            float wv = Won[k*DIMC + c];
            #pragma unroll
            for (int r = 0; r < 8; r++) acc[r] += g_agg[(row0+r)*DIMC + k] * wv;
        }
        #pragma unroll
        for (int r = 0; r < 8; r++)
            sx2[r][c] = acc[r] + bon[c] + g_x1[(row0+r)*DIMC + c];
    }
    __syncthreads();
    {
        int w = tid >> 5, lane = tid & 31;
        float s = 0.f, sq = 0.f;
        #pragma unroll
        for (int u = 0; u < 8; u++){ float v = sx2[w][lane+u*32]; s += v; sq += v*v; }
        #pragma unroll
        for (int o = 16; o > 0; o >>= 1){ s += __shfl_xor_sync(~0u,s,o); sq += __shfl_xor_sync(~0u,sq,o); }
        float mean = s*(1.f/256.f);
        float rstd = rsqrtf(sq*(1.f/256.f) - mean*mean + EPSV);
        #pragma unroll
        for (int u = 0; u < 8; u++){
            int cc = lane + u*32;
            sx2[w][cc] = (sx2[w][cc]-mean)*rstd*ln3s[cc] + ln3b[cc];
        }
    }
    __syncthreads();
    {
        float hacc[8][4] = {};
        for (int k = 0; k < DIMC; k++){
            float xv[8];
            #pragma unroll
            for (int r = 0; r < 8; r++) xv[r] = sx2[r][k];
            #pragma unroll
            for (int m = 0; m < 4; m++){
                float wv = w1[(size_t)k*HID + tid + m*256];
                #pragma unroll
                for (int r = 0; r < 8; r++) hacc[r][m] += xv[r]*wv;
            }
        }
        #pragma unroll
        for (int m = 0; m < 4; m++){
            float bb = b1[tid + m*256];
            #pragma unroll
            for (int r = 0; r < 8; r++) sh[r][tid+m*256] = fmaxf(hacc[r][m] + bb, 0.f);
        }
    }
    __syncthreads();
    {
        float acc[8] = {};
        for (int k = 0; k < HID; k++){
            float wv = w2[k*DIMC + c];
            #pragma unroll
            for (int r = 0; r < 8; r++) acc[r] += sh[r][k]*wv;
        }
        __syncthreads();
        #pragma unroll
        for (int r = 0; r < 8; r++)
            sh[r][c] = acc[r] + b2[c] + sx2[r][c];
    }
    __syncthreads();
    {
        int w = tid >> 5, lane = tid & 31;
        float s = 0.f, sq = 0.f;
        #pragma unroll
        for (int u = 0; u < 8; u++){ float v = sh[w][lane+u*32]; s += v; sq += v*v; }
        #pragma unroll
        for (int o = 16; o > 0; o >>= 1){ s += __shfl_xor_sync(~0u,s,o); sq += __shfl_xor_sync(~0u,sq,o); }
        float mean = s*(1.f/256.f);
        float rstd = rsqrtf(sq*(1.f/256.f) - mean*mean + EPSV);
        #pragma unroll
        for (int u = 0; u < 8; u++){
            int cc = lane + u*32;
            xout[(size_t)(row0+w)*DIMC + cc] = (sh[w][cc]-mean)*rstd*ln5s[cc] + ln5b[cc];
        }
    }
}

// ================= launch =================
extern "C" void kernel_launch(void* const* d_in, const int* in_sizes, int n_in,
                              void* d_out, int out_size)
{
    const float* x    = (const float*)d_in[0];
    const float* y    = (const float*)d_in[1];
    const float* Wq   = (const float*)d_in[2];  const float* bq  = (const float*)d_in[3];
    const float* Wk   = (const float*)d_in[4];  const float* bk  = (const float*)d_in[5];
    const float* Wv   = (const float*)d_in[6];  const float* bv  = (const float*)d_in[7];
    const float* We   = (const float*)d_in[8];  const float* be  = (const float*)d_in[9];
    const float* Woe  = (const float*)d_in[10]; const float* boe = (const float*)d_in[11];
    const float* Won  = (const float*)d_in[12]; const float* bon = (const float*)d_in[13];
    const float* m1w1 = (const float*)d_in[14]; const float* m1b1= (const float*)d_in[15];
    const float* m1w2 = (const float*)d_in[16]; const float* m1b2= (const float*)d_in[17];
    const float* m2w1 = (const float*)d_in[18]; const float* m2b1= (const float*)d_in[19];
    const float* m2w2 = (const float*)d_in[20]; const float* m2b2= (const float*)d_in[21];
    const float* ln1s = (const float*)d_in[22]; const float* ln1b= (const float*)d_in[23];
    const float* ln3s = (const float*)d_in[24]; const float* ln3b= (const float*)d_in[25];
    const float* ln4s = (const float*)d_in[26]; const float* ln4b= (const float*)d_in[27];
    const float* ln5s = (const float*)d_in[28]; const float* ln5b= (const float*)d_in[29];
    const float* ln6s = (const float*)d_in[30]; const float* ln6b= (const float*)d_in[31];

    float* out  = (float*)d_out;
    float* xout = out;                               // (8,128,256)
    float* yout = out + BAT*NTOK*DIMC;               // (8,128,128,256)

    int smem = (128*LDA + 128*LDH + 5120 + 256 + 256 + 256) * (int)sizeof(float); // 224256
    cudaFuncSetAttribute(edge_kernel, cudaFuncAttributeMaxDynamicSharedMemorySize, smem);

    prep_kernel<<<1024, 256>>>(We, Woe, m2w1, m2w2);
    node_pre_kernel<<<BAT*NTOK/4, 256>>>(x, Wq, bq, Wk, bk, Wv, bv, ln1s, ln1b);
    edge_kernel<<<BAT*NTOK, 256, smem>>>(y, be, boe, m2b1, m2b2,
                                         ln4s, ln4b, ln6s, ln6b, yout);
    node_post_kernel<<<BAT*NTOK/8, 256>>>(Won, bon, m1w1, m1b1, m1w2, m1b2,
                                          ln3s, ln3b, ln5s, ln5b, xout);
}

// round 5
// speedup vs baseline: 3.1670x; 1.3450x over previous
#include <cuda_runtime.h>
#include <math.h>
#include <stdint.h>

#define DIMC 256
#define NTOK 128
#define BAT  8
#define HID  1024
#define EPSV 1e-5f
#define ASCALE 0.17677669529663687f

#define LDA 260    // sA row stride (floats)
#define LDH 132    // sH row stride
#define LDB1 36    // B chunk stride (32-wide k chunks)
#define LDB2 20    // B chunk stride (16-wide k chunks)

// -------- device scratch --------
__device__ float g_x1 [BAT*NTOK*DIMC];
__device__ float g_q  [BAT*NTOK*DIMC];
__device__ float g_k  [BAT*NTOK*DIMC];
__device__ float g_v  [BAT*NTOK*DIMC];
__device__ float g_agg[BAT*NTOK*DIMC];
__device__ float g_WeT [DIMC*DIMC];   // [n=256][k=256]
__device__ float g_WoeT[DIMC*DIMC];   // [n=256][k=256]
__device__ float g_W1T [HID*DIMC];    // [n=1024][k=256]
__device__ float g_W2T [DIMC*HID];    // [n=256][k=1024]

// -------- helpers --------
__device__ __forceinline__ float rna_tf32(float x){
    uint32_t r;
    asm("cvt.rna.tf32.f32 %0, %1;" : "=r"(r) : "f"(x));
    return __uint_as_float(r);
}
__device__ __forceinline__ void mma8(float* d, const uint32_t* a, const uint32_t* b){
    asm volatile("mma.sync.aligned.m16n8k8.row.col.f32.tf32.tf32.f32 "
        "{%0,%1,%2,%3},{%4,%5,%6,%7},{%8,%9},{%0,%1,%2,%3};"
        : "+f"(d[0]),"+f"(d[1]),"+f"(d[2]),"+f"(d[3])
        : "r"(a[0]),"r"(a[1]),"r"(a[2]),"r"(a[3]),"r"(b[0]),"r"(b[1]));
}
__device__ __forceinline__ void ldsm4(uint32_t* r, uint32_t addr){
    asm volatile("ldmatrix.sync.aligned.m8n8.x4.shared.b16 {%0,%1,%2,%3}, [%4];"
        : "=r"(r[0]),"=r"(r[1]),"=r"(r[2]),"=r"(r[3]) : "r"(addr));
}

// Generic k-chunked GEMM pass, 512 threads.
// A resident in smem (ldmatrix base precomputed per lane).
// B prefetched global->regs->smem, double-phased to hide latency.
// Warp computes MF*16 rows x NF*8 cols.
template<int NF, int LDB, int KCH, int MF>
__device__ __forceinline__ void gemm_run(
    uint32_t aBase, int lda,
    const float* __restrict__ gB, int ldgb, int kglob0, int nkc,
    float* sB, uint32_t bBase,
    float c[MF][NF][4], int tid)
{
    const int F4 = KCH/4;
    float4 pf[2];
    #pragma unroll
    for (int j = 0; j < 2; j++){
        int i = tid + j*512, n = i/F4, q = i%F4;
        pf[j] = *(const float4*)(gB + (size_t)n*ldgb + kglob0 + q*4);
    }
    for (int kc = 0; kc < nkc; kc++){
        __syncthreads();
        #pragma unroll
        for (int j = 0; j < 2; j++){
            int i = tid + j*512, n = i/F4, q = i%F4;
            *(float4*)(sB + n*LDB + q*4) = pf[j];
        }
        __syncthreads();
        if (kc + 1 < nkc){
            #pragma unroll
            for (int j = 0; j < 2; j++){
                int i = tid + j*512, n = i/F4, q = i%F4;
                pf[j] = *(const float4*)(gB + (size_t)n*ldgb + kglob0 + (kc+1)*KCH + q*4);
            }
        }
        #pragma unroll
        for (int ks = 0; ks < KCH/8; ks++){
            int kk = kc*KCH + ks*8;
            uint32_t a[MF][4];
            #pragma unroll
            for (int mf = 0; mf < MF; mf++)
                ldsm4(a[mf], aBase + (uint32_t)(mf*16*lda + kk)*4u);
            #pragma unroll
            for (int np = 0; np < NF/2; np++){
                uint32_t b4[4];
                ldsm4(b4, bBase + (uint32_t)(np*16*LDB + ks*8)*4u);
                #pragma unroll
                for (int mf = 0; mf < MF; mf++){
                    mma8(c[mf][2*np+0], a[mf], b4);
                    mma8(c[mf][2*np+1], a[mf], b4+2);
                }
            }
        }
    }
}

#define ZEROC(c, MF, NF) { _Pragma("unroll") for (int _m=0;_m<MF;_m++) _Pragma("unroll") for (int _n=0;_n<NF;_n++) _Pragma("unroll") for (int _u=0;_u<4;_u++) (c)[_m][_n][_u]=0.f; }

// ================= prep: transpose + tf32-round weights =================
__global__ __launch_bounds__(256) void prep_kernel(
    const float* __restrict__ We, const float* __restrict__ Woe,
    const float* __restrict__ w1, const float* __restrict__ w2)
{
    int idx = blockIdx.x*256 + threadIdx.x;   // 0..262143
    if (idx < DIMC*DIMC){
        int n = idx >> 8, k = idx & 255;
        g_WeT [idx] = rna_tf32(We [k*DIMC + n]);
        g_WoeT[idx] = rna_tf32(Woe[k*DIMC + n]);
    }
    {   int n = idx >> 8, k = idx & 255;
        g_W1T[idx] = rna_tf32(w1[(size_t)k*HID + n]); }
    {   int n = idx >> 10, k = idx & 1023;
        g_W2T[idx] = rna_tf32(w2[(size_t)k*DIMC + n]); }
}

// ================= kernel 1: LN1 + q/k/v =================
__global__ __launch_bounds__(256) void node_pre_kernel(
    const float* __restrict__ x,
    const float* __restrict__ Wq, const float* __restrict__ bq,
    const float* __restrict__ Wk, const float* __restrict__ bk,
    const float* __restrict__ Wv, const float* __restrict__ bv,
    const float* __restrict__ ln1s, const float* __restrict__ ln1b)
{
    __shared__ float sx[4][DIMC];
    int tid = threadIdx.x;
    int row0 = blockIdx.x * 4;
    int w = tid >> 5, lane = tid & 31;
    if (w < 4){
        const float* xr = x + (size_t)(row0 + w) * DIMC;
        float vals[8], s = 0.f, sq = 0.f;
        #pragma unroll
        for (int u = 0; u < 8; u++){ vals[u] = xr[lane + u*32]; s += vals[u]; sq += vals[u]*vals[u]; }
        #pragma unroll
        for (int o = 16; o > 0; o >>= 1){ s += __shfl_xor_sync(~0u,s,o); sq += __shfl_xor_sync(~0u,sq,o); }
        float mean = s * (1.f/DIMC);
        float rstd = rsqrtf(sq*(1.f/DIMC) - mean*mean + EPSV);
        #pragma unroll
        for (int u = 0; u < 8; u++){
            int c = lane + u*32;
            float v = (vals[u]-mean)*rstd*ln1s[c] + ln1b[c];
            sx[w][c] = v;
            g_x1[(row0+w)*DIMC + c] = v;
        }
    }
    __syncthreads();
    int c = tid;
    float aq[4] = {}, ak[4] = {}, av[4] = {};
    for (int k = 0; k < DIMC; k++){
        float wq = Wq[k*DIMC+c], wk = Wk[k*DIMC+c], wv = Wv[k*DIMC+c];
        #pragma unroll
        for (int r = 0; r < 4; r++){
            float xv = sx[r][k];
            aq[r] += xv*wq; ak[r] += xv*wk; av[r] += xv*wv;
        }
    }
    #pragma unroll
    for (int r = 0; r < 4; r++){
        int gr = row0 + r;
        g_q[gr*DIMC + c] = aq[r] + bq[c];
        g_k[gr*DIMC + c] = ak[r] + bk[c];
        g_v[gr*DIMC + c] = av[r] + bv[c];
    }
}

// ================= kernel 2: edge mega-kernel (mma.sync tf32, 512 thr) =================
__global__ __launch_bounds__(512, 1) void edge_kernel(
    const float* __restrict__ y,
    const float* __restrict__ be,  const float* __restrict__ boe,
    const float* __restrict__ b1,  const float* __restrict__ b2,
    const float* __restrict__ ln4s, const float* __restrict__ ln4b,
    const float* __restrict__ ln6s, const float* __restrict__ ln6b,
    float* __restrict__ yout)
{
    extern __shared__ float sm[];
    float* sA  = sm;                   // 128*260 = 33280
    float* sH  = sA + 128*LDA;         // 128*132 = 16896
    float* sB  = sH + 128*LDH;         // 5120
    float* sS  = sB + 5120;            // 512
    float* sAg = sS + 512;             // 512
    float* sQ  = sAg + 512;            // 256

    int tid = threadIdx.x, lane = tid & 31, w = tid >> 5;
    int wm = (w >> 2) * 32, wn = w & 3;
    int g = lane >> 2, t = lane & 3;
    int bi = blockIdx.x, b = bi >> 7;
    const float* yblk = y + (size_t)bi * NTOK * DIMC;

    // lane-resolved ldmatrix bases
    int sub = lane >> 3, rin = lane & 7;
    uint32_t smemA = (uint32_t)__cvta_generic_to_shared(sA);
    uint32_t smemH = (uint32_t)__cvta_generic_to_shared(sH);
    uint32_t smemB = (uint32_t)__cvta_generic_to_shared(sB);
    uint32_t aA  = smemA + (uint32_t)(((wm + rin + (sub&1)*8)*LDA + (sub>>1)*4)*4);
    uint32_t aH  = smemH + (uint32_t)(((wm + rin + (sub&1)*8)*LDH + (sub>>1)*4)*4);
    uint32_t bB1 = smemB + (uint32_t)(((wn*32 + (sub>>1)*8 + rin)*LDB1 + (sub&1)*4)*4);
    uint32_t bB2 = smemB + (uint32_t)(((wn*64 + (sub>>1)*8 + rin)*LDB2 + (sub&1)*4)*4);

    if (tid < 256) sQ[tid] = g_q[bi*DIMC + tid];
    // stage y -> sA (raw fp32; HMMA truncates to tf32)
    for (int i = tid; i < 128*64; i += 512){
        int r = i >> 6, kq = (i & 63) << 2;
        *(float4*)(sA + r*LDA + kq) = *(const float4*)(yblk + r*DIMC + kq);
    }

    float cE[2][2][4][4];

    // ---- GEMM1: e = y @ We ----
    #pragma unroll
    for (int nc = 0; nc < 2; nc++){
        ZEROC(cE[nc], 2, 4);
        gemm_run<4, LDB1, 32, 2>(aA, LDA, g_WeT + nc*128*DIMC, DIMC, 0, 8,
                                 sB, bB1, cE[nc], tid);
    }
    __syncthreads();
    // epilogue: attn = q*k*scale*(e+1)*e -> sA
    #pragma unroll
    for (int nc = 0; nc < 2; nc++)
    #pragma unroll
    for (int mf = 0; mf < 2; mf++)
    #pragma unroll
    for (int nf = 0; nf < 4; nf++)
    #pragma unroll
    for (int hh = 0; hh < 2; hh++){
        int r = wm + mf*16 + g + hh*8;
        int col = nc*128 + wn*32 + nf*8 + 2*t;
        float e0 = cE[nc][mf][nf][2*hh+0] + be[col];
        float e1 = cE[nc][mf][nf][2*hh+1] + be[col+1];
        const float* kp = g_k + (size_t)(b*NTOK + r)*DIMC + col;
        sA[r*LDA + col]     = sQ[col]  *kp[0]*ASCALE*(e0 + 1.f)*e0;
        sA[r*LDA + col + 1] = sQ[col+1]*kp[1]*ASCALE*(e1 + 1.f)*e1;
    }
    __syncthreads();

    // ---- softmax over j + agg (2-way row split over 512 threads) ----
    {
        int half = tid >> 8, c = tid & 255;
        int j0 = half*64;
        float mx = -1e30f;
        for (int j = j0; j < j0+64; j++) mx = fmaxf(mx, sA[j*LDA + c]);
        sS[tid] = mx;
        __syncthreads();
        float M = fmaxf(sS[c], sS[256 + c]);
        float s = 0.f, agv = 0.f;
        for (int j = j0; j < j0+64; j++){
            float p = __expf(sA[j*LDA + c] - M);
            s += p;
            agv += p * g_v[(size_t)(b*NTOK + j)*DIMC + c];
        }
        __syncthreads();
        sS[tid] = s; sAg[tid] = agv;
        __syncthreads();
        if (tid < 256)
            g_agg[bi*DIMC + tid] = (sAg[tid] + sAg[256+tid]) / (sS[tid] + sS[256+tid]);
    }

    // ---- GEMM2: edge_out = attn @ Woe ----
    #pragma unroll
    for (int nc = 0; nc < 2; nc++){
        ZEROC(cE[nc], 2, 4);
        gemm_run<4, LDB1, 32, 2>(aA, LDA, g_WoeT + nc*128*DIMC, DIMC, 0, 8,
                                 sB, bB1, cE[nc], tid);
    }
    __syncthreads();
    // epilogue: y2_pre = d + boe + y -> sA
    #pragma unroll
    for (int nc = 0; nc < 2; nc++)
    #pragma unroll
    for (int mf = 0; mf < 2; mf++)
    #pragma unroll
    for (int nf = 0; nf < 4; nf++)
    #pragma unroll
    for (int hh = 0; hh < 2; hh++){
        int r = wm + mf*16 + g + hh*8;
        int col = nc*128 + wn*32 + nf*8 + 2*t;
        const float* yp = yblk + (size_t)r*DIMC + col;
        sA[r*LDA + col]     = cE[nc][mf][nf][2*hh+0] + boe[col]   + yp[0];
        sA[r*LDA + col + 1] = cE[nc][mf][nf][2*hh+1] + boe[col+1] + yp[1];
    }
    __syncthreads();

    // ---- LN4 -> y2 (in place, quad-shuffle) ----
    {
        int r = tid >> 2, q = tid & 3;
        float* base = sA + r*LDA + q*64;
        float s = 0.f, sq = 0.f;
        #pragma unroll 8
        for (int i = 0; i < 64; i++){ float v = base[i]; s += v; sq += v*v; }
        s += __shfl_xor_sync(~0u, s, 1); sq += __shfl_xor_sync(~0u, sq, 1);
        s += __shfl_xor_sync(~0u, s, 2); sq += __shfl_xor_sync(~0u, sq, 2);
        float mean = s * (1.f/256.f);
        float rstd = rsqrtf(sq*(1.f/256.f) - mean*mean + EPSV);
        const float* s4 = ln4s + q*64;
        const float* b4v = ln4b + q*64;
        #pragma unroll 8
        for (int i = 0; i < 64; i++)
            base[i] = (base[i] - mean)*rstd*s4[i] + b4v[i];
    }
    __syncthreads();

    // ---- MLP: GEMM3 (h tile into sH) interleaved with GEMM4 (accumulate) ----
    float cM[2][8][4];
    ZEROC(cM, 2, 8);
    for (int ht = 0; ht < 8; ht++){
        float cH[2][4][4];
        ZEROC(cH, 2, 4);
        gemm_run<4, LDB1, 32, 2>(aA, LDA, g_W1T + (size_t)ht*128*DIMC, DIMC, 0, 8,
                                 sB, bB1, cH, tid);
        // write h tile (per-warp exclusive region; ordering handled by gemm_run barriers)
        #pragma unroll
        for (int mf = 0; mf < 2; mf++)
        #pragma unroll
        for (int nf = 0; nf < 4; nf++)
        #pragma unroll
        for (int hh = 0; hh < 2; hh++){
            int r = wm + mf*16 + g + hh*8;
            int col = wn*32 + nf*8 + 2*t;
            sH[r*LDH + col]     = fmaxf(cH[mf][nf][2*hh+0] + b1[ht*128 + col],     0.f);
            sH[r*LDH + col + 1] = fmaxf(cH[mf][nf][2*hh+1] + b1[ht*128 + col + 1], 0.f);
        }
        gemm_run<8, LDB2, 16, 2>(aH, LDH, g_W2T, HID, ht*128, 8,
                                 sB, bB2, cM, tid);
    }
    // GEMM4 epilogue: sA = y2 + mlp + b2 (per-warp exclusive tiles)
    #pragma unroll
    for (int mf = 0; mf < 2; mf++)
    #pragma unroll
    for (int nf = 0; nf < 8; nf++)
    #pragma unroll
    for (int hh = 0; hh < 2; hh++){
        int r = wm + mf*16 + g + hh*8;
        int col = wn*64 + nf*8 + 2*t;
        sA[r*LDA + col]     += cM[mf][nf][2*hh+0] + b2[col];
        sA[r*LDA + col + 1] += cM[mf][nf][2*hh+1] + b2[col+1];
    }
    __syncthreads();

    // ---- LN6 -> yout (quad-shuffle) ----
    {
        int r = tid >> 2, q = tid & 3;
        float* base = sA + r*LDA + q*64;
        float s = 0.f, sq = 0.f;
        #pragma unroll 8
        for (int i = 0; i < 64; i++){ float v = base[i]; s += v; sq += v*v; }
        s += __shfl_xor_sync(~0u, s, 1); sq += __shfl_xor_sync(~0u, sq, 1);
        s += __shfl_xor_sync(~0u, s, 2); sq += __shfl_xor_sync(~0u, sq, 2);
        float mean = s * (1.f/256.f);
        float rstd = rsqrtf(sq*(1.f/256.f) - mean*mean + EPSV);
        float* op = yout + (size_t)bi*NTOK*DIMC + (size_t)r*DIMC + q*64;
        const float* s6 = ln6s + q*64;
        const float* b6 = ln6b + q*64;
        #pragma unroll 8
        for (int i = 0; i < 64; i++)
            op[i] = (base[i] - mean)*rstd*s6[i] + b6[i];
    }
}

// ================= kernel 3: node path finish (4 rows/CTA, 256 CTAs) =================
__global__ __launch_bounds__(256) void node_post_kernel(
    const float* __restrict__ Won, const float* __restrict__ bon,
    const float* __restrict__ w1,  const float* __restrict__ b1,
    const float* __restrict__ w2,  const float* __restrict__ b2,
    const float* __restrict__ ln3s, const float* __restrict__ ln3b,
    const float* __restrict__ ln5s, const float* __restrict__ ln5b,
    float* __restrict__ xout)
{
    __shared__ float sx2[4][DIMC];
    __shared__ float sh[4][HID];
    int tid = threadIdx.x;
    int row0 = blockIdx.x * 4;
    int c = tid;
    {
        float acc[4] = {};
        for (int k = 0; k < DIMC; k++){
            float wv = Won[k*DIMC + c];
            #pragma unroll
            for (int r = 0; r < 4; r++) acc[r] += g_agg[(row0+r)*DIMC + k] * wv;
        }
        #pragma unroll
        for (int r = 0; r < 4; r++)
            sx2[r][c] = acc[r] + bon[c] + g_x1[(row0+r)*DIMC + c];
    }
    __syncthreads();
    {
        int w = tid >> 5, lane = tid & 31;
        if (w < 4){
            float s = 0.f, sq = 0.f;
            #pragma unroll
            for (int u = 0; u < 8; u++){ float v = sx2[w][lane+u*32]; s += v; sq += v*v; }
            #pragma unroll
            for (int o = 16; o > 0; o >>= 1){ s += __shfl_xor_sync(~0u,s,o); sq += __shfl_xor_sync(~0u,sq,o); }
            float mean = s*(1.f/256.f);
            float rstd = rsqrtf(sq*(1.f/256.f) - mean*mean + EPSV);
            #pragma unroll
            for (int u = 0; u < 8; u++){
                int cc = lane + u*32;
                sx2[w][cc] = (sx2[w][cc]-mean)*rstd*ln3s[cc] + ln3b[cc];
            }
        }
    }
    __syncthreads();
    {
        float hacc[4][4] = {};
        for (int k = 0; k < DIMC; k++){
            float xv[4];
            #pragma unroll
            for (int r = 0; r < 4; r++) xv[r] = sx2[r][k];
            #pragma unroll
            for (int m = 0; m < 4; m++){
                float wv = w1[(size_t)k*HID + tid + m*256];
                #pragma unroll
                for (int r = 0; r < 4; r++) hacc[r][m] += xv[r]*wv;
            }
        }
        #pragma unroll
        for (int m = 0; m < 4; m++){
            float bb = b1[tid + m*256];
            #pragma unroll
            for (int r = 0; r < 4; r++) sh[r][tid+m*256] = fmaxf(hacc[r][m] + bb, 0.f);
        }
    }
    __syncthreads();
    {
        float acc[4] = {};
        for (int k = 0; k < HID; k++){
            float wv = w2[k*DIMC + c];
            #pragma unroll
            for (int r = 0; r < 4; r++) acc[r] += sh[r][k]*wv;
        }
        __syncthreads();
        #pragma unroll
        for (int r = 0; r < 4; r++)
            sh[r][c] = acc[r] + b2[c] + sx2[r][c];
    }
    __syncthreads();
    {
        int w = tid >> 5, lane = tid & 31;
        if (w < 4){
            float s = 0.f, sq = 0.f;
            #pragma unroll
            for (int u = 0; u < 8; u++){ float v = sh[w][lane+u*32]; s += v; sq += v*v; }
            #pragma unroll
            for (int o = 16; o > 0; o >>= 1){ s += __shfl_xor_sync(~0u,s,o); sq += __shfl_xor_sync(~0u,sq,o); }
            float mean = s*(1.f/256.f);
            float rstd = rsqrtf(sq*(1.f/256.f) - mean*mean + EPSV);
            #pragma unroll
            for (int u = 0; u < 8; u++){
                int cc = lane + u*32;
                xout[(size_t)(row0+w)*DIMC + cc] = (sh[w][cc]-mean)*rstd*ln5s[cc] + ln5b[cc];
            }
        }
    }
}

// ================= launch =================
extern "C" void kernel_launch(void* const* d_in, const int* in_sizes, int n_in,
                              void* d_out, int out_size)
{
    const float* x    = (const float*)d_in[0];
    const float* y    = (const float*)d_in[1];
    const float* Wq   = (const float*)d_in[2];  const float* bq  = (const float*)d_in[3];
    const float* Wk   = (const float*)d_in[4];  const float* bk  = (const float*)d_in[5];
    const float* Wv   = (const float*)d_in[6];  const float* bv  = (const float*)d_in[7];
    const float* We   = (const float*)d_in[8];  const float* be  = (const float*)d_in[9];
    const float* Woe  = (const float*)d_in[10]; const float* boe = (const float*)d_in[11];
    const float* Won  = (const float*)d_in[12]; const float* bon = (const float*)d_in[13];
    const float* m1w1 = (const float*)d_in[14]; const float* m1b1= (const float*)d_in[15];
    const float* m1w2 = (const float*)d_in[16]; const float* m1b2= (const float*)d_in[17];
    const float* m2w1 = (const float*)d_in[18]; const float* m2b1= (const float*)d_in[19];
    const float* m2w2 = (const float*)d_in[20]; const float* m2b2= (const float*)d_in[21];
    const float* ln1s = (const float*)d_in[22]; const float* ln1b= (const float*)d_in[23];
    const float* ln3s = (const float*)d_in[24]; const float* ln3b= (const float*)d_in[25];
    const float* ln4s = (const float*)d_in[26]; const float* ln4b= (const float*)d_in[27];
    const float* ln5s = (const float*)d_in[28]; const float* ln5b= (const float*)d_in[29];
    const float* ln6s = (const float*)d_in[30]; const float* ln6b= (const float*)d_in[31];

    float* out  = (float*)d_out;
    float* xout = out;                               // (8,128,256)
    float* yout = out + BAT*NTOK*DIMC;               // (8,128,128,256)

    int smem = (128*LDA + 128*LDH + 5120 + 512 + 512 + 256) * (int)sizeof(float); // 226304
    cudaFuncSetAttribute(edge_kernel, cudaFuncAttributeMaxDynamicSharedMemorySize, smem);

    prep_kernel<<<1024, 256>>>(We, Woe, m2w1, m2w2);
    node_pre_kernel<<<BAT*NTOK/4, 256>>>(x, Wq, bq, Wk, bk, Wv, bv, ln1s, ln1b);
    edge_kernel<<<BAT*NTOK, 512, smem>>>(y, be, boe, m2b1, m2b2,
                                         ln4s, ln4b, ln6s, ln6b, yout);
    node_post_kernel<<<BAT*NTOK/4, 256>>>(Won, bon, m1w1, m1b1, m1w2, m1b2,
                                          ln3s, ln3b, ln5s, ln5b, xout);
}

// round 7
// speedup vs baseline: 6.4356x; 2.0321x over previous
#include <cuda_runtime.h>
#include <cuda_fp16.h>
#include <math.h>
#include <stdint.h>

#define DIMC 256
#define NTOK 128
#define BAT  8
#define HID  1024
#define EPSV 1e-5f
#define ASCALE 0.17677669529663687f

#define LDAh 264    // sAh row stride (halfs): 528B -> +4 banks/row, conflict-free ldsm
#define LDHh 136    // sHh row stride (halfs): 272B
#define LDBh 72     // B chunk row stride (halfs): 144B
#define KCH  64     // k per chunk (halfs)
#define BUFSZ 18432 // 128*72*2 bytes per B buffer

// -------- device scratch --------
__device__ float g_x1 [BAT*NTOK*DIMC];
__device__ float g_q  [BAT*NTOK*DIMC];
__device__ float g_k  [BAT*NTOK*DIMC];
__device__ float g_v  [BAT*NTOK*DIMC];
__device__ float g_agg[BAT*NTOK*DIMC];
__device__ __half g_WeH [DIMC*DIMC];   // [n=256][k=256]
__device__ __half g_WoeH[DIMC*DIMC];   // [n=256][k=256]
__device__ __half g_W1H [HID*DIMC];    // [n=1024][k=256]
__device__ __half g_W2H [DIMC*HID];    // [n=256][k=1024]

// -------- PTX helpers --------
__device__ __forceinline__ void mma16(float* d, const uint32_t* a, const uint32_t* b){
    asm volatile("mma.sync.aligned.m16n8k16.row.col.f32.f16.f16.f32 "
        "{%0,%1,%2,%3},{%4,%5,%6,%7},{%8,%9},{%0,%1,%2,%3};"
        : "+f"(d[0]),"+f"(d[1]),"+f"(d[2]),"+f"(d[3])
        : "r"(a[0]),"r"(a[1]),"r"(a[2]),"r"(a[3]),"r"(b[0]),"r"(b[1]));
}
__device__ __forceinline__ void ldsm4(uint32_t* r, uint32_t addr){
    asm volatile("ldmatrix.sync.aligned.m8n8.x4.shared.b16 {%0,%1,%2,%3}, [%4];"
        : "=r"(r[0]),"=r"(r[1]),"=r"(r[2]),"=r"(r[3]) : "r"(addr));
}
__device__ __forceinline__ void cpa16(uint32_t dst, const void* src){
    asm volatile("cp.async.cg.shared.global [%0], [%1], 16;" :: "r"(dst), "l"(src));
}
#define CP_COMMIT() asm volatile("cp.async.commit_group;" ::: "memory")
#define CP_WAIT(n)  asm volatile("cp.async.wait_group %0;" :: "n"(n) : "memory")

#define ZEROC(c, MF, NF) { _Pragma("unroll") for (int _m=0;_m<MF;_m++) _Pragma("unroll") for (int _n=0;_n<NF;_n++) _Pragma("unroll") for (int _u=0;_u<4;_u++) (c)[_m][_n][_u]=0.f; }

// k-chunked GEMM, 512 threads, fp16 operands, fp32 accum; 2-deep cp.async ring.
__device__ __forceinline__ void gemm_h(
    uint32_t aLane, int ldah,
    const __half* __restrict__ gB, int ldgb, int k0, int nkc,
    uint32_t sB_u, uint32_t bLane,
    float c[2][4][4], int tid)
{
    const __half* src0 = gB + k0;
    #define STAGE(kc, s) { \
        const __half* _s = src0 + (kc)*KCH; \
        uint32_t _d = sB_u + (uint32_t)(s)*BUFSZ; \
        _Pragma("unroll") \
        for (int _j = 0; _j < 2; _j++){ \
            int _ii = tid + _j*512; \
            int _n = _ii >> 3, _q = _ii & 7; \
            cpa16(_d + (uint32_t)(_n*LDBh + _q*8)*2, _s + (size_t)_n*ldgb + _q*8); \
        } \
        CP_COMMIT(); }
    STAGE(0, 0);
    for (int kc = 0; kc < nkc; kc++){
        __syncthreads();                       // prev compute done; next slot free
        if (kc + 1 < nkc){ STAGE(kc+1, (kc+1)&1); CP_WAIT(1); }
        else             { CP_WAIT(0); }
        __syncthreads();                       // chunk kc visible to all
        uint32_t bBuf = bLane + (uint32_t)(kc & 1)*BUFSZ;
        #pragma unroll
        for (int ks = 0; ks < KCH/16; ks++){
            uint32_t a[2][4];
            #pragma unroll
            for (int mf = 0; mf < 2; mf++)
                ldsm4(a[mf], aLane + (uint32_t)(mf*16*ldah + kc*KCH + ks*16)*2);
            #pragma unroll
            for (int np = 0; np < 2; np++){
                uint32_t b4[4];
                ldsm4(b4, bBuf + (uint32_t)(np*16*LDBh + ks*16)*2);
                uint32_t bx[2] = { b4[0], b4[2] };
                uint32_t by[2] = { b4[1], b4[3] };
                #pragma unroll
                for (int mf = 0; mf < 2; mf++){
                    mma16(c[mf][2*np+0], a[mf], bx);
                    mma16(c[mf][2*np+1], a[mf], by);
                }
            }
        }
    }
    #undef STAGE
}

// ================= prep: transpose + fp16 weights =================
__global__ __launch_bounds__(256) void prep_kernel(
    const float* __restrict__ We, const float* __restrict__ Woe,
    const float* __restrict__ w1, const float* __restrict__ w2)
{
    int idx = blockIdx.x*256 + threadIdx.x;   // 0..262143
    if (idx < DIMC*DIMC){
        int n = idx >> 8, k = idx & 255;
        g_WeH [idx] = __float2half_rn(We [k*DIMC + n]);
        g_WoeH[idx] = __float2half_rn(Woe[k*DIMC + n]);
    }
    {   int n = idx >> 8, k = idx & 255;
        g_W1H[idx] = __float2half_rn(w1[(size_t)k*HID + n]); }
    {   int n = idx >> 10, k = idx & 1023;
        g_W2H[idx] = __float2half_rn(w2[(size_t)k*DIMC + n]); }
}

// ================= kernel 1: LN1 + q/k/v =================
__global__ __launch_bounds__(256) void node_pre_kernel(
    const float* __restrict__ x,
    const float* __restrict__ Wq, const float* __restrict__ bq,
    const float* __restrict__ Wk, const float* __restrict__ bk,
    const float* __restrict__ Wv, const float* __restrict__ bv,
    const float* __restrict__ ln1s, const float* __restrict__ ln1b)
{
    __shared__ float sx[4][DIMC];
    int tid = threadIdx.x;
    int row0 = blockIdx.x * 4;
    int w = tid >> 5, lane = tid & 31;
    if (w < 4){
        const float* xr = x + (size_t)(row0 + w) * DIMC;
        float vals[8], s = 0.f, sq = 0.f;
        #pragma unroll
        for (int u = 0; u < 8; u++){ vals[u] = xr[lane + u*32]; s += vals[u]; sq += vals[u]*vals[u]; }
        #pragma unroll
        for (int o = 16; o > 0; o >>= 1){ s += __shfl_xor_sync(~0u,s,o); sq += __shfl_xor_sync(~0u,sq,o); }
        float mean = s * (1.f/DIMC);
        float rstd = rsqrtf(sq*(1.f/DIMC) - mean*mean + EPSV);
        #pragma unroll
        for (int u = 0; u < 8; u++){
            int c = lane + u*32;
            float v = (vals[u]-mean)*rstd*ln1s[c] + ln1b[c];
            sx[w][c] = v;
            g_x1[(row0+w)*DIMC + c] = v;
        }
    }
    __syncthreads();
    int c = tid;
    float aq[4] = {}, ak[4] = {}, av[4] = {};
    for (int k = 0; k < DIMC; k++){
        float wq = Wq[k*DIMC+c], wk = Wk[k*DIMC+c], wv = Wv[k*DIMC+c];
        #pragma unroll
        for (int r = 0; r < 4; r++){
            float xv = sx[r][k];
            aq[r] += xv*wq; ak[r] += xv*wk; av[r] += xv*wv;
        }
    }
    #pragma unroll
    for (int r = 0; r < 4; r++){
        int gr = row0 + r;
        g_q[gr*DIMC + c] = aq[r] + bq[c];
        g_k[gr*DIMC + c] = ak[r] + bk[c];
        g_v[gr*DIMC + c] = av[r] + bv[c];
    }
}

// ================= kernel 2: edge mega-kernel (fp16 mma, fp32 residuals) =================
__global__ __launch_bounds__(512, 1) void edge_kernel(
    const float* __restrict__ y,
    const float* __restrict__ be,  const float* __restrict__ boe,
    const float* __restrict__ b1,  const float* __restrict__ b2,
    const float* __restrict__ ln4s, const float* __restrict__ ln4b,
    const float* __restrict__ ln6s, const float* __restrict__ ln6b,
    float* __restrict__ yout)
{
    extern __shared__ char smem[];
    __half* sAh = (__half*)smem;                    // 67584 (y/attn/y2-hi fp16 tile)
    __half* sRh = (__half*)(smem + 67584);          // 67584 (y2 fp16 lo tile)
    __half* sHh = (__half*)(smem + 135168);         // 34816 (h tile)
    char*   sBc = smem + 169984;                    // 36864 (2x18432 B ring)
    float*  sS  = (float*)(smem + 206848);          // 512 f (softmax max/sum; LN partial sums)
    float*  sAg = (float*)(smem + 208896);          // 512 f (softmax agg;    LN partial sqs)
    float*  sQ  = (float*)(smem + 210944);          // 256 f

    uint32_t sA_u = (uint32_t)__cvta_generic_to_shared(sAh);
    uint32_t sH_u = (uint32_t)__cvta_generic_to_shared(sHh);
    uint32_t sB_u = (uint32_t)__cvta_generic_to_shared(sBc);

    int tid = threadIdx.x, lane = tid & 31, w = tid >> 5;
    int wm = (w >> 2) * 32, wn = w & 3;
    int g = lane >> 2, t = lane & 3;
    int sub = lane >> 3, rin = lane & 7;
    int bi = blockIdx.x, b = bi >> 7;
    const float* yblk = y + (size_t)bi * NTOK * DIMC;

    uint32_t aLaneA = sA_u + (uint32_t)(((wm + (sub&1)*8 + rin)*LDAh + (sub>>1)*8)*2);
    uint32_t aLaneH = sH_u + (uint32_t)(((wm + (sub&1)*8 + rin)*LDHh + (sub>>1)*8)*2);
    uint32_t bLane  = sB_u + (uint32_t)(((wn*32 + (sub&1)*8 + rin)*LDBh + (sub>>1)*8)*2);

    if (tid < 256) sQ[tid] = g_q[bi*DIMC + tid] * ASCALE;
    // stage y -> fp16 sAh (operand only; fp32 y re-read from global for residual)
    {
        const float4* y4 = (const float4*)yblk;
        for (int i = tid; i < 8192; i += 512){
            int r = i >> 6, kq = (i & 63) << 2;
            float4 v = y4[i];
            __half2* d = (__half2*)(sAh + r*LDAh + kq);
            d[0] = __floats2half2_rn(v.x, v.y);
            d[1] = __floats2half2_rn(v.z, v.w);
        }
    }

    float cE0[2][4][4], cE1[2][4][4];

    // ---- GEMM1: e = y @ We ----
    ZEROC(cE0, 2, 4); ZEROC(cE1, 2, 4);
    gemm_h(aLaneA, LDAh, g_WeH,            DIMC, 0, 4, sB_u, bLane, cE0, tid);
    gemm_h(aLaneA, LDAh, g_WeH + 128*DIMC, DIMC, 0, 4, sB_u, bLane, cE1, tid);
    __syncthreads();
    // epilogue: attn = (q*scale)*k*(e+1)*e -> sAh fp16 (GEMM2 operand + softmax; proven OK)
    #pragma unroll
    for (int nc = 0; nc < 2; nc++)
    #pragma unroll
    for (int mf = 0; mf < 2; mf++)
    #pragma unroll
    for (int nf = 0; nf < 4; nf++)
    #pragma unroll
    for (int hh = 0; hh < 2; hh++){
        float* cc = nc ? cE1[mf][nf] : cE0[mf][nf];
        int r = wm + mf*16 + g + hh*8;
        int col = nc*128 + wn*32 + nf*8 + 2*t;
        float e0 = cc[2*hh+0] + be[col];
        float e1 = cc[2*hh+1] + be[col+1];
        float2 kv = *(const float2*)(g_k + (size_t)(b*NTOK + r)*DIMC + col);
        float v0 = sQ[col]  *kv.x*(e0 + 1.f)*e0;
        float v1 = sQ[col+1]*kv.y*(e1 + 1.f)*e1;
        *(__half2*)(sAh + r*LDAh + col) = __floats2half2_rn(v0, v1);
    }
    __syncthreads();

    // ---- softmax over j + agg (2-way row split) ----
    {
        int half_ = tid >> 8, c = tid & 255;
        int j0 = half_*64;
        float mx = -1e30f;
        for (int j = j0; j < j0+64; j++) mx = fmaxf(mx, __half2float(sAh[j*LDAh + c]));
        sS[tid] = mx;
        __syncthreads();
        float M = fmaxf(sS[c], sS[256 + c]);
        float s = 0.f, agv = 0.f;
        for (int j = j0; j < j0+64; j++){
            float p = __expf(__half2float(sAh[j*LDAh + c]) - M);
            s += p;
            agv += p * g_v[(size_t)(b*NTOK + j)*DIMC + c];
        }
        __syncthreads();
        sS[tid] = s; sAg[tid] = agv;
        __syncthreads();
        if (tid < 256)
            g_agg[bi*DIMC + tid] = (sAg[tid] + sAg[256+tid]) / (sS[tid] + sS[256+tid]);
        __syncthreads();
    }

    // ---- GEMM2: edge_out = attn @ Woe ----
    ZEROC(cE0, 2, 4); ZEROC(cE1, 2, 4);
    gemm_h(aLaneA, LDAh, g_WoeH,            DIMC, 0, 4, sB_u, bLane, cE0, tid);
    gemm_h(aLaneA, LDAh, g_WoeH + 128*DIMC, DIMC, 0, 4, sB_u, bLane, cE1, tid);

    // ---- epilogue2 + LN4 fully in fp32 registers ----
    {
        float ps[2][2] = {}, pq[2][2] = {};
        #pragma unroll
        for (int nc = 0; nc < 2; nc++)
        #pragma unroll
        for (int mf = 0; mf < 2; mf++)
        #pragma unroll
        for (int nf = 0; nf < 4; nf++)
        #pragma unroll
        for (int hh = 0; hh < 2; hh++){
            float* cc = nc ? cE1[mf][nf] : cE0[mf][nf];
            int r = wm + mf*16 + g + hh*8;
            int col = nc*128 + wn*32 + nf*8 + 2*t;
            float2 yv = *(const float2*)(yblk + (size_t)r*DIMC + col);
            float v0 = cc[2*hh+0] + boe[col]   + yv.x;
            float v1 = cc[2*hh+1] + boe[col+1] + yv.y;
            cc[2*hh+0] = v0; cc[2*hh+1] = v1;
            ps[mf][hh] += v0 + v1; pq[mf][hh] += v0*v0 + v1*v1;
        }
        #pragma unroll
        for (int mf = 0; mf < 2; mf++)
        #pragma unroll
        for (int hh = 0; hh < 2; hh++){
            ps[mf][hh] += __shfl_xor_sync(~0u, ps[mf][hh], 1);
            ps[mf][hh] += __shfl_xor_sync(~0u, ps[mf][hh], 2);
            pq[mf][hh] += __shfl_xor_sync(~0u, pq[mf][hh], 1);
            pq[mf][hh] += __shfl_xor_sync(~0u, pq[mf][hh], 2);
        }
        // cross-warp (wn) partials; ALSO serves as the "GEMM2 compute all done" barrier
        if (t == 0){
            #pragma unroll
            for (int mf = 0; mf < 2; mf++)
            #pragma unroll
            for (int hh = 0; hh < 2; hh++){
                int r = wm + mf*16 + g + hh*8;
                sS [wn*128 + r] = ps[mf][hh];
                sAg[wn*128 + r] = pq[mf][hh];
            }
        }
        __syncthreads();
        #pragma unroll
        for (int mf = 0; mf < 2; mf++)
        #pragma unroll
        for (int hh = 0; hh < 2; hh++){
            int r = wm + mf*16 + g + hh*8;
            float S = sS[r] + sS[128+r] + sS[256+r] + sS[384+r];
            float Q = sAg[r] + sAg[128+r] + sAg[256+r] + sAg[384+r];
            float mean = S * (1.f/256.f);
            float rstd = rsqrtf(Q*(1.f/256.f) - mean*mean + EPSV);
            #pragma unroll
            for (int nc = 0; nc < 2; nc++)
            #pragma unroll
            for (int nf = 0; nf < 4; nf++){
                float* cc = nc ? cE1[mf][nf] : cE0[mf][nf];
                int col = nc*128 + wn*32 + nf*8 + 2*t;
                float v0 = (cc[2*hh+0] - mean)*rstd*ln4s[col]   + ln4b[col];
                float v1 = (cc[2*hh+1] - mean)*rstd*ln4s[col+1] + ln4b[col+1];
                __half h0 = __float2half_rn(v0), h1 = __float2half_rn(v1);
                *(__half2*)(sAh + r*LDAh + col) = __halves2half2(h0, h1);
                *(__half2*)(sRh + r*LDAh + col) =
                    __floats2half2_rn(v0 - __half2float(h0), v1 - __half2float(h1));
            }
        }
    }

    // ---- MLP: GEMM3 (h tiles) interleaved with GEMM4 (accumulate cM) ----
    float cM0[2][4][4], cM1[2][4][4];
    ZEROC(cM0, 2, 4); ZEROC(cM1, 2, 4);
    for (int ht = 0; ht < 8; ht++){
        float cH[2][4][4];
        ZEROC(cH, 2, 4);
        gemm_h(aLaneA, LDAh, g_W1H + (size_t)ht*128*DIMC, DIMC, 0, 4, sB_u, bLane, cH, tid);
        #pragma unroll
        for (int mf = 0; mf < 2; mf++)
        #pragma unroll
        for (int nf = 0; nf < 4; nf++)
        #pragma unroll
        for (int hh = 0; hh < 2; hh++){
            int r = wm + mf*16 + g + hh*8;
            int col = wn*32 + nf*8 + 2*t;
            float h0 = fmaxf(cH[mf][nf][2*hh+0] + b1[ht*128 + col],     0.f);
            float h1 = fmaxf(cH[mf][nf][2*hh+1] + b1[ht*128 + col + 1], 0.f);
            *(__half2*)(sHh + r*LDHh + col) = __floats2half2_rn(h0, h1);
        }
        gemm_h(aLaneH, LDHh, g_W2H,                   HID, ht*128, 2, sB_u, bLane, cM0, tid);
        gemm_h(aLaneH, LDHh, g_W2H + (size_t)128*HID, HID, ht*128, 2, sB_u, bLane, cM1, tid);
    }

    // ---- LN6 fully in fp32 registers -> yout ----
    {
        float ps[2][2] = {}, pq[2][2] = {};
        #pragma unroll
        for (int nc = 0; nc < 2; nc++)
        #pragma unroll
        for (int mf = 0; mf < 2; mf++)
        #pragma unroll
        for (int nf = 0; nf < 4; nf++)
        #pragma unroll
        for (int hh = 0; hh < 2; hh++){
            float* cc = nc ? cM1[mf][nf] : cM0[mf][nf];
            int r = wm + mf*16 + g + hh*8;
            int col = nc*128 + wn*32 + nf*8 + 2*t;
            float2 hi = __half22float2(*(__half2*)(sAh + r*LDAh + col));
            float2 lo = __half22float2(*(__half2*)(sRh + r*LDAh + col));
            float v0 = cc[2*hh+0] + b2[col]   + hi.x + lo.x;
            float v1 = cc[2*hh+1] + b2[col+1] + hi.y + lo.y;
            cc[2*hh+0] = v0; cc[2*hh+1] = v1;
            ps[mf][hh] += v0 + v1; pq[mf][hh] += v0*v0 + v1*v1;
        }
        #pragma unroll
        for (int mf = 0; mf < 2; mf++)
        #pragma unroll
        for (int hh = 0; hh < 2; hh++){
            ps[mf][hh] += __shfl_xor_sync(~0u, ps[mf][hh], 1);
            ps[mf][hh] += __shfl_xor_sync(~0u, ps[mf][hh], 2);
            pq[mf][hh] += __shfl_xor_sync(~0u, pq[mf][hh], 1);
            pq[mf][hh] += __shfl_xor_sync(~0u, pq[mf][hh], 2);
        }
        __syncthreads();   // all GEMM4 done; sS/sAg free for reuse
        if (t == 0){
            #pragma unroll
            for (int mf = 0; mf < 2; mf++)
            #pragma unroll
            for (int hh = 0; hh < 2; hh++){
                int r = wm + mf*16 + g + hh*8;
                sS [wn*128 + r] = ps[mf][hh];
                sAg[wn*128 + r] = pq[mf][hh];
            }
        }
        __syncthreads();
        float* youtb = yout + (size_t)bi*NTOK*DIMC;
        #pragma unroll
        for (int mf = 0; mf < 2; mf++)
        #pragma unroll
        for (int hh = 0; hh < 2; hh++){
            int r = wm + mf*16 + g + hh*8;
            float S = sS[r] + sS[128+r] + sS[256+r] + sS[384+r];
            float Q = sAg[r] + sAg[128+r] + sAg[256+r] + sAg[384+r];
            float mean = S * (1.f/256.f);
            float rstd = rsqrtf(Q*(1.f/256.f) - mean*mean + EPSV);
            #pragma unroll
            for (int nc = 0; nc < 2; nc++)
            #pragma unroll
            for (int nf = 0; nf < 4; nf++){
                float* cc = nc ? cM1[mf][nf] : cM0[mf][nf];
                int col = nc*128 + wn*32 + nf*8 + 2*t;
                float v0 = (cc[2*hh+0] - mean)*rstd*ln6s[col]   + ln6b[col];
                float v1 = (cc[2*hh+1] - mean)*rstd*ln6s[col+1] + ln6b[col+1];
                *(float2*)(youtb + (size_t)r*DIMC + col) = make_float2(v0, v1);
            }
        }
    }
}

// ================= kernel 3: node path finish (512 thr, split-k) =================
__global__ __launch_bounds__(512) void node_post_kernel(
    const float* __restrict__ Won, const float* __restrict__ bon,
    const float* __restrict__ w1,  const float* __restrict__ b1,
    const float* __restrict__ w2,  const float* __restrict__ b2,
    const float* __restrict__ ln3s, const float* __restrict__ ln3b,
    const float* __restrict__ ln5s, const float* __restrict__ ln5b,
    float* __restrict__ xout)
{
    __shared__ float sx2[4][DIMC];
    __shared__ float st [4][DIMC];
    __shared__ float sh [4][HID];
    int tid = threadIdx.x;
    int kh = tid >> 8, c = tid & 255;
    int row0 = blockIdx.x * 4;

    {
        float acc[4] = {};
        for (int k = kh*128; k < kh*128 + 128; k++){
            float wv = Won[k*DIMC + c];
            #pragma unroll
            for (int r = 0; r < 4; r++) acc[r] += g_agg[(row0+r)*DIMC + k] * wv;
        }
        if (kh == 0){
            #pragma unroll
            for (int r = 0; r < 4; r++) st[r][c] = acc[r];
        }
        __syncthreads();
        if (kh == 1){
            #pragma unroll
            for (int r = 0; r < 4; r++)
                sx2[r][c] = st[r][c] + acc[r] + bon[c] + g_x1[(row0+r)*DIMC + c];
        }
        __syncthreads();
    }
    if (tid < 128){
        int w = tid >> 5, lane = tid & 31;
        float s = 0.f, sq = 0.f;
        #pragma unroll
        for (int u = 0; u < 8; u++){ float v = sx2[w][lane+u*32]; s += v; sq += v*v; }
        #pragma unroll
        for (int o = 16; o > 0; o >>= 1){ s += __shfl_xor_sync(~0u,s,o); sq += __shfl_xor_sync(~0u,sq,o); }
        float mean = s*(1.f/256.f);
        float rstd = rsqrtf(sq*(1.f/256.f) - mean*mean + EPSV);
        #pragma unroll
        for (int u = 0; u < 8; u++){
            int cc = lane + u*32;
            sx2[w][cc] = (sx2[w][cc]-mean)*rstd*ln3s[cc] + ln3b[cc];
        }
    }
    __syncthreads();
    {
        float hacc[4][2] = {};
        for (int k = 0; k < DIMC; k++){
            float xv[4];
            #pragma unroll
            for (int r = 0; r < 4; r++) xv[r] = sx2[r][k];
            #pragma unroll
            for (int m = 0; m < 2; m++){
                float wv = w1[(size_t)k*HID + tid + m*512];
                #pragma unroll
                for (int r = 0; r < 4; r++) hacc[r][m] += xv[r]*wv;
            }
        }
        #pragma unroll
        for (int m = 0; m < 2; m++){
            float bb = b1[tid + m*512];
            #pragma unroll
            for (int r = 0; r < 4; r++) sh[r][tid + m*512] = fmaxf(hacc[r][m] + bb, 0.f);
        }
    }
    __syncthreads();
    {
        float acc[4] = {};
        for (int k = kh*512; k < kh*512 + 512; k++){
            float wv = w2[k*DIMC + c];
            #pragma unroll
            for (int r = 0; r < 4; r++) acc[r] += sh[r][k]*wv;
        }
        if (kh == 0){
            #pragma unroll
            for (int r = 0; r < 4; r++) st[r][c] = acc[r];
        }
        __syncthreads();
        if (kh == 1){
            #pragma unroll
            for (int r = 0; r < 4; r++)
                st[r][c] = st[r][c] + acc[r] + b2[c] + sx2[r][c];
        }
        __syncthreads();
    }
    if (tid < 128){
        int w = tid >> 5, lane = tid & 31;
        float s = 0.f, sq = 0.f;
        #pragma unroll
        for (int u = 0; u < 8; u++){ float v = st[w][lane+u*32]; s += v; sq += v*v; }
        #pragma unroll
        for (int o = 16; o > 0; o >>= 1){ s += __shfl_xor_sync(~0u,s,o); sq += __shfl_xor_sync(~0u,sq,o); }
        float mean = s*(1.f/256.f);
        float rstd = rsqrtf(sq*(1.f/256.f) - mean*mean + EPSV);
        #pragma unroll
        for (int u = 0; u < 8; u++){
            int cc = lane + u*32;
            xout[(size_t)(row0+w)*DIMC + cc] = (st[w][cc]-mean)*rstd*ln5s[cc] + ln5b[cc];
        }
    }
}

// ================= launch =================
extern "C" void kernel_launch(void* const* d_in, const int* in_sizes, int n_in,
                              void* d_out, int out_size)
{
    const float* x    = (const float*)d_in[0];
    const float* y    = (const float*)d_in[1];
    const float* Wq   = (const float*)d_in[2];  const float* bq  = (const float*)d_in[3];
    const float* Wk   = (const float*)d_in[4];  const float* bk  = (const float*)d_in[5];
    const float* Wv   = (const float*)d_in[6];  const float* bv  = (const float*)d_in[7];
    const float* We   = (const float*)d_in[8];  const float* be  = (const float*)d_in[9];
    const float* Woe  = (const float*)d_in[10]; const float* boe = (const float*)d_in[11];
    const float* Won  = (const float*)d_in[12]; const float* bon = (const float*)d_in[13];
    const float* m1w1 = (const float*)d_in[14]; const float* m1b1= (const float*)d_in[15];
    const float* m1w2 = (const float*)d_in[16]; const float* m1b2= (const float*)d_in[17];
    const float* m2w1 = (const float*)d_in[18]; const float* m2b1= (const float*)d_in[19];
    const float* m2w2 = (const float*)d_in[20]; const float* m2b2= (const float*)d_in[21];
    const float* ln1s = (const float*)d_in[22]; const float* ln1b= (const float*)d_in[23];
    const float* ln3s = (const float*)d_in[24]; const float* ln3b= (const float*)d_in[25];
    const float* ln4s = (const float*)d_in[26]; const float* ln4b= (const float*)d_in[27];
    const float* ln5s = (const float*)d_in[28]; const float* ln5b= (const float*)d_in[29];
    const float* ln6s = (const float*)d_in[30]; const float* ln6b= (const float*)d_in[31];

    float* out  = (float*)d_out;
    float* xout = out;                               // (8,128,256)
    float* yout = out + BAT*NTOK*DIMC;               // (8,128,128,256)

    int smem = 211968;
    cudaFuncSetAttribute(edge_kernel, cudaFuncAttributeMaxDynamicSharedMemorySize, smem);

    prep_kernel<<<1024, 256>>>(We, Woe, m2w1, m2w2);
    node_pre_kernel<<<BAT*NTOK/4, 256>>>(x, Wq, bq, Wk, bk, Wv, bv, ln1s, ln1b);
    edge_kernel<<<BAT*NTOK, 512, smem>>>(y, be, boe, m2b1, m2b2,
                                         ln4s, ln4b, ln6s, ln6b, yout);
    node_post_kernel<<<BAT*NTOK/4, 512>>>(Won, bon, m1w1, m1b1, m1w2, m1b2,
                                          ln3s, ln3b, ln5s, ln5b, xout);
}

// round 9
// speedup vs baseline: 7.6242x; 1.1847x over previous
#include <cuda_runtime.h>
#include <cuda_fp16.h>
#include <math.h>
#include <stdint.h>

#define DIMC 256
#define NTOK 128
#define BAT  8
#define HID  1024
#define EPSV 1e-5f
#define ASCALE 0.17677669529663687f

#define LDAh 264    // sAh row stride (halfs)
#define LDHh 136    // sHh row stride (halfs)
#define LDBh 72     // B chunk row stride (halfs)
#define KCH  64     // k per chunk (halfs)
#define BUFSZ 18432 // bytes per B buffer

// -------- device scratch --------
__device__ float g_x1 [BAT*NTOK*DIMC];
__device__ float g_q  [BAT*NTOK*DIMC];
__device__ float g_k  [BAT*NTOK*DIMC];
__device__ float g_v  [BAT*NTOK*DIMC];
__device__ float g_agg[BAT*NTOK*DIMC];
__device__ __half g_WeH [DIMC*DIMC];    // edge We   [n=256][k=256]
__device__ __half g_WoeH[DIMC*DIMC];    // edge Woe  [n=256][k=256]
__device__ __half g_W1H [HID*DIMC];     // EDGE mlp2_w1 [n=1024][k=256]
__device__ __half g_W2H [DIMC*HID];     // EDGE mlp2_w2 [n=256][k=1024]
__device__ __half g_N1H [HID*DIMC];     // NODE mlp1_w1 [n=1024][k=256]
__device__ __half g_N2H [DIMC*HID];     // NODE mlp1_w2 [n=256][k=1024]
__device__ __half g_WonH[DIMC*DIMC];    // Won [n=256][k=256]
__device__ __half g_QKVH[3*DIMC*DIMC];  // [n=768][k=256] (q,k,v stacked)

// -------- PTX helpers --------
__device__ __forceinline__ void mma16(float* d, const uint32_t* a, const uint32_t* b){
    asm volatile("mma.sync.aligned.m16n8k16.row.col.f32.f16.f16.f32 "
        "{%0,%1,%2,%3},{%4,%5,%6,%7},{%8,%9},{%0,%1,%2,%3};"
        : "+f"(d[0]),"+f"(d[1]),"+f"(d[2]),"+f"(d[3])
        : "r"(a[0]),"r"(a[1]),"r"(a[2]),"r"(a[3]),"r"(b[0]),"r"(b[1]));
}
__device__ __forceinline__ void ldsm4(uint32_t* r, uint32_t addr){
    asm volatile("ldmatrix.sync.aligned.m8n8.x4.shared.b16 {%0,%1,%2,%3}, [%4];"
        : "=r"(r[0]),"=r"(r[1]),"=r"(r[2]),"=r"(r[3]) : "r"(addr));
}
__device__ __forceinline__ void cpa16(uint32_t dst, const void* src){
    asm volatile("cp.async.cg.shared.global [%0], [%1], 16;" :: "r"(dst), "l"(src));
}
#define CP_COMMIT() asm volatile("cp.async.commit_group;" ::: "memory")
#define CP_WAIT(n)  asm volatile("cp.async.wait_group %0;" :: "n"(n) : "memory")

#define ZEROC(c, MF, NF) { _Pragma("unroll") for (int _m=0;_m<MF;_m++) _Pragma("unroll") for (int _n=0;_n<NF;_n++) _Pragma("unroll") for (int _u=0;_u<4;_u++) (c)[_m][_n][_u]=0.f; }

// k-chunked GEMM, 512 threads, fp16 operands, fp32 accum; 2-deep cp.async ring.
__device__ __forceinline__ void gemm_h(
    uint32_t aLane, int ldah,
    const __half* __restrict__ gB, int ldgb, int k0, int nkc,
    uint32_t sB_u, uint32_t bLane,
    float c[2][4][4], int tid)
{
    const __half* src0 = gB + k0;
    #define STAGE(kc, s) { \
        const __half* _s = src0 + (kc)*KCH; \
        uint32_t _d = sB_u + (uint32_t)(s)*BUFSZ; \
        _Pragma("unroll") \
        for (int _j = 0; _j < 2; _j++){ \
            int _ii = tid + _j*512; \
            int _n = _ii >> 3, _q = _ii & 7; \
            cpa16(_d + (uint32_t)(_n*LDBh + _q*8)*2, _s + (size_t)_n*ldgb + _q*8); \
        } \
        CP_COMMIT(); }
    STAGE(0, 0);
    for (int kc = 0; kc < nkc; kc++){
        __syncthreads();
        if (kc + 1 < nkc){ STAGE(kc+1, (kc+1)&1); CP_WAIT(1); }
        else             { CP_WAIT(0); }
        __syncthreads();
        uint32_t bBuf = bLane + (uint32_t)(kc & 1)*BUFSZ;
        #pragma unroll
        for (int ks = 0; ks < KCH/16; ks++){
            uint32_t a[2][4];
            #pragma unroll
            for (int mf = 0; mf < 2; mf++)
                ldsm4(a[mf], aLane + (uint32_t)(mf*16*ldah + kc*KCH + ks*16)*2);
            #pragma unroll
            for (int np = 0; np < 2; np++){
                uint32_t b4[4];
                ldsm4(b4, bBuf + (uint32_t)(np*16*LDBh + ks*16)*2);
                uint32_t bx[2] = { b4[0], b4[2] };
                uint32_t by[2] = { b4[1], b4[3] };
                #pragma unroll
                for (int mf = 0; mf < 2; mf++){
                    mma16(c[mf][2*np+0], a[mf], bx);
                    mma16(c[mf][2*np+1], a[mf], by);
                }
            }
        }
    }
    #undef STAGE
}

// ================= prep: transpose + fp16 weights =================
__global__ __launch_bounds__(256) void prep_kernel(
    const float* __restrict__ We, const float* __restrict__ Woe,
    const float* __restrict__ w1, const float* __restrict__ w2,
    const float* __restrict__ n1, const float* __restrict__ n2,
    const float* __restrict__ Won,
    const float* __restrict__ Wq, const float* __restrict__ Wk,
    const float* __restrict__ Wv)
{
    int idx = blockIdx.x*256 + threadIdx.x;   // 0..262143
    if (idx < DIMC*DIMC){
        int n = idx >> 8, k = idx & 255;
        g_WeH [idx] = __float2half_rn(We [k*DIMC + n]);
        g_WoeH[idx] = __float2half_rn(Woe[k*DIMC + n]);
        g_WonH[idx] = __float2half_rn(Won[k*DIMC + n]);
    }
    {   int n = idx >> 8, k = idx & 255;
        g_W1H[idx] = __float2half_rn(w1[(size_t)k*HID + n]);
        g_N1H[idx] = __float2half_rn(n1[(size_t)k*HID + n]); }
    {   int n = idx >> 10, k = idx & 1023;
        g_W2H[idx] = __float2half_rn(w2[(size_t)k*DIMC + n]);
        g_N2H[idx] = __float2half_rn(n2[(size_t)k*DIMC + n]); }
    if (idx < 3*DIMC*DIMC){
        int n = idx >> 8, k = idx & 255;
        int mat = n >> 8, col = n & 255;
        const float* W = (mat == 0) ? Wq : (mat == 1) ? Wk : Wv;
        g_QKVH[idx] = __float2half_rn(W[k*DIMC + col]);
    }
}

// ================= kernel 1: LN1 + q/k/v (fp16 mma, 8 rows/CTA) =================
__global__ __launch_bounds__(256) void node_pre_kernel(
    const float* __restrict__ x,
    const float* __restrict__ bq, const float* __restrict__ bk,
    const float* __restrict__ bv,
    const float* __restrict__ ln1s, const float* __restrict__ ln1b)
{
    __shared__ __align__(16) __half sA[16*LDAh];
    int tid = threadIdx.x, lane = tid & 31, w = tid >> 5;
    int r0 = blockIdx.x * 8;
    int sub = lane >> 3, rin = lane & 7;

    // LN1: warp w -> row r0+w
    {
        const float* xr = x + (size_t)(r0 + w) * DIMC;
        float vals[8], s = 0.f, sq = 0.f;
        #pragma unroll
        for (int u = 0; u < 8; u++){ vals[u] = xr[lane + u*32]; s += vals[u]; sq += vals[u]*vals[u]; }
        #pragma unroll
        for (int o = 16; o > 0; o >>= 1){ s += __shfl_xor_sync(~0u,s,o); sq += __shfl_xor_sync(~0u,sq,o); }
        float mean = s * (1.f/DIMC);
        float rstd = rsqrtf(sq*(1.f/DIMC) - mean*mean + EPSV);
        #pragma unroll
        for (int u = 0; u < 8; u++){
            int c = lane + u*32;
            float v = (vals[u]-mean)*rstd*ln1s[c] + ln1b[c];
            g_x1[(r0+w)*DIMC + c] = v;
            sA[w*LDAh + c] = __float2half_rn(v);
        }
    }
    for (int i = tid; i < 8*LDAh; i += 256) sA[8*LDAh + i] = __float2half_rn(0.f);
    __syncthreads();

    uint32_t aLane = (uint32_t)__cvta_generic_to_shared(sA)
                   + (uint32_t)((((sub&1)*8 + rin)*LDAh + (sub>>1)*8)*2);
    int g = lane >> 2, t2 = (lane & 3)*2;

    #pragma unroll
    for (int pass = 0; pass < 3; pass++){
        float c[4][4];
        #pragma unroll
        for (int nf = 0; nf < 4; nf++)
            #pragma unroll
            for (int u = 0; u < 4; u++) c[nf][u] = 0.f;
        const __half* base = g_QKVH + (size_t)(pass*256 + w*32 + (lane>>2))*DIMC + (lane&3)*2;
        #pragma unroll
        for (int kk = 0; kk < 16; kk++){
            uint32_t a[4];
            ldsm4(a, aLane + (uint32_t)(kk*16*2));
            #pragma unroll
            for (int nf = 0; nf < 4; nf++){
                const __half* bp = base + (size_t)nf*8*DIMC + kk*16;
                uint32_t b[2] = { *(const uint32_t*)bp, *(const uint32_t*)(bp + 8) };
                mma16(c[nf], a, b);
            }
        }
        const float* bias = (pass == 0) ? bq : (pass == 1) ? bk : bv;
        float* dst = (pass == 0) ? g_q : (pass == 1) ? g_k : g_v;
        #pragma unroll
        for (int nf = 0; nf < 4; nf++){
            int col = w*32 + nf*8 + t2;
            *(float2*)(dst + (size_t)(r0+g)*DIMC + col) =
                make_float2(c[nf][0] + bias[col], c[nf][1] + bias[col+1]);
        }
    }
}

// ================= kernel 2: edge mega-kernel (fp16 mma, fp32 residuals) =================
__global__ __launch_bounds__(512, 1) void edge_kernel(
    const float* __restrict__ y,
    const float* __restrict__ be,  const float* __restrict__ boe,
    const float* __restrict__ b1,  const float* __restrict__ b2,
    const float* __restrict__ ln4s, const float* __restrict__ ln4b,
    const float* __restrict__ ln6s, const float* __restrict__ ln6b,
    float* __restrict__ yout)
{
    extern __shared__ char smem[];
    __half* sAh = (__half*)smem;                    // 67584
    __half* sRh = (__half*)(smem + 67584);          // 67584
    __half* sHh = (__half*)(smem + 135168);         // 34816
    char*   sBc = smem + 169984;                    // 36864
    float*  sS  = (float*)(smem + 206848);          // 512 f
    float*  sAg = (float*)(smem + 208896);          // 512 f
    float*  sQ  = (float*)(smem + 210944);          // 256 f

    uint32_t sA_u = (uint32_t)__cvta_generic_to_shared(sAh);
    uint32_t sH_u = (uint32_t)__cvta_generic_to_shared(sHh);
    uint32_t sB_u = (uint32_t)__cvta_generic_to_shared(sBc);

    int tid = threadIdx.x, lane = tid & 31, w = tid >> 5;
    int wm = (w >> 2) * 32, wn = w & 3;
    int g = lane >> 2, t = lane & 3;
    int sub = lane >> 3, rin = lane & 7;
    int bi = blockIdx.x, b = bi >> 7;
    const float* yblk = y + (size_t)bi * NTOK * DIMC;

    uint32_t aLaneA = sA_u + (uint32_t)(((wm + (sub&1)*8 + rin)*LDAh + (sub>>1)*8)*2);
    uint32_t aLaneH = sH_u + (uint32_t)(((wm + (sub&1)*8 + rin)*LDHh + (sub>>1)*8)*2);
    uint32_t bLane  = sB_u + (uint32_t)(((wn*32 + (sub&1)*8 + rin)*LDBh + (sub>>1)*8)*2);

    if (tid < 256) sQ[tid] = g_q[bi*DIMC + tid] * ASCALE;
    {
        const float4* y4 = (const float4*)yblk;
        for (int i = tid; i < 8192; i += 512){
            int r = i >> 6, kq = (i & 63) << 2;
            float4 v = y4[i];
            __half2* d = (__half2*)(sAh + r*LDAh + kq);
            d[0] = __floats2half2_rn(v.x, v.y);
            d[1] = __floats2half2_rn(v.z, v.w);
        }
    }

    float cE0[2][4][4], cE1[2][4][4];

    // ---- GEMM1: e = y @ We ----
    ZEROC(cE0, 2, 4); ZEROC(cE1, 2, 4);
    gemm_h(aLaneA, LDAh, g_WeH,            DIMC, 0, 4, sB_u, bLane, cE0, tid);
    gemm_h(aLaneA, LDAh, g_WeH + 128*DIMC, DIMC, 0, 4, sB_u, bLane, cE1, tid);
    __syncthreads();
    #pragma unroll
    for (int nc = 0; nc < 2; nc++)
    #pragma unroll
    for (int mf = 0; mf < 2; mf++)
    #pragma unroll
    for (int nf = 0; nf < 4; nf++)
    #pragma unroll
    for (int hh = 0; hh < 2; hh++){
        float* cc = nc ? cE1[mf][nf] : cE0[mf][nf];
        int r = wm + mf*16 + g + hh*8;
        int col = nc*128 + wn*32 + nf*8 + 2*t;
        float e0 = cc[2*hh+0] + be[col];
        float e1 = cc[2*hh+1] + be[col+1];
        float2 kv = *(const float2*)(g_k + (size_t)(b*NTOK + r)*DIMC + col);
        float v0 = sQ[col]  *kv.x*(e0 + 1.f)*e0;
        float v1 = sQ[col+1]*kv.y*(e1 + 1.f)*e1;
        *(__half2*)(sAh + r*LDAh + col) = __floats2half2_rn(v0, v1);
    }
    __syncthreads();

    // ---- softmax over j + agg ----
    {
        int half_ = tid >> 8, c = tid & 255;
        int j0 = half_*64;
        float mx = -1e30f;
        for (int j = j0; j < j0+64; j++) mx = fmaxf(mx, __half2float(sAh[j*LDAh + c]));
        sS[tid] = mx;
        __syncthreads();
        float M = fmaxf(sS[c], sS[256 + c]);
        float s = 0.f, agv = 0.f;
        for (int j = j0; j < j0+64; j++){
            float p = __expf(__half2float(sAh[j*LDAh + c]) - M);
            s += p;
            agv += p * g_v[(size_t)(b*NTOK + j)*DIMC + c];
        }
        __syncthreads();
        sS[tid] = s; sAg[tid] = agv;
        __syncthreads();
        if (tid < 256)
            g_agg[bi*DIMC + tid] = (sAg[tid] + sAg[256+tid]) / (sS[tid] + sS[256+tid]);
        __syncthreads();
    }

    // ---- GEMM2: edge_out = attn @ Woe ----
    ZEROC(cE0, 2, 4); ZEROC(cE1, 2, 4);
    gemm_h(aLaneA, LDAh, g_WoeH,            DIMC, 0, 4, sB_u, bLane, cE0, tid);
    gemm_h(aLaneA, LDAh, g_WoeH + 128*DIMC, DIMC, 0, 4, sB_u, bLane, cE1, tid);

    // ---- epilogue2 + LN4 in fp32 registers ----
    {
        float ps[2][2] = {}, pq[2][2] = {};
        #pragma unroll
        for (int nc = 0; nc < 2; nc++)
        #pragma unroll
        for (int mf = 0; mf < 2; mf++)
        #pragma unroll
        for (int nf = 0; nf < 4; nf++)
        #pragma unroll
        for (int hh = 0; hh < 2; hh++){
            float* cc = nc ? cE1[mf][nf] : cE0[mf][nf];
            int r = wm + mf*16 + g + hh*8;
            int col = nc*128 + wn*32 + nf*8 + 2*t;
            float2 yv = *(const float2*)(yblk + (size_t)r*DIMC + col);
            float v0 = cc[2*hh+0] + boe[col]   + yv.x;
            float v1 = cc[2*hh+1] + boe[col+1] + yv.y;
            cc[2*hh+0] = v0; cc[2*hh+1] = v1;
            ps[mf][hh] += v0 + v1; pq[mf][hh] += v0*v0 + v1*v1;
        }
        #pragma unroll
        for (int mf = 0; mf < 2; mf++)
        #pragma unroll
        for (int hh = 0; hh < 2; hh++){
            ps[mf][hh] += __shfl_xor_sync(~0u, ps[mf][hh], 1);
            ps[mf][hh] += __shfl_xor_sync(~0u, ps[mf][hh], 2);
            pq[mf][hh] += __shfl_xor_sync(~0u, pq[mf][hh], 1);
            pq[mf][hh] += __shfl_xor_sync(~0u, pq[mf][hh], 2);
        }
        if (t == 0){
            #pragma unroll
            for (int mf = 0; mf < 2; mf++)
            #pragma unroll
            for (int hh = 0; hh < 2; hh++){
                int r = wm + mf*16 + g + hh*8;
                sS [wn*128 + r] = ps[mf][hh];
                sAg[wn*128 + r] = pq[mf][hh];
            }
        }
        __syncthreads();
        #pragma unroll
        for (int mf = 0; mf < 2; mf++)
        #pragma unroll
        for (int hh = 0; hh < 2; hh++){
            int r = wm + mf*16 + g + hh*8;
            float S = sS[r] + sS[128+r] + sS[256+r] + sS[384+r];
            float Q = sAg[r] + sAg[128+r] + sAg[256+r] + sAg[384+r];
            float mean = S * (1.f/256.f);
            float rstd = rsqrtf(Q*(1.f/256.f) - mean*mean + EPSV);
            #pragma unroll
            for (int nc = 0; nc < 2; nc++)
            #pragma unroll
            for (int nf = 0; nf < 4; nf++){
                float* cc = nc ? cE1[mf][nf] : cE0[mf][nf];
                int col = nc*128 + wn*32 + nf*8 + 2*t;
                float v0 = (cc[2*hh+0] - mean)*rstd*ln4s[col]   + ln4b[col];
                float v1 = (cc[2*hh+1] - mean)*rstd*ln4s[col+1] + ln4b[col+1];
                __half h0 = __float2half_rn(v0), h1 = __float2half_rn(v1);
                *(__half2*)(sAh + r*LDAh + col) = __halves2half2(h0, h1);
                *(__half2*)(sRh + r*LDAh + col) =
                    __floats2half2_rn(v0 - __half2float(h0), v1 - __half2float(h1));
            }
        }
    }

    // ---- MLP ----
    float cM0[2][4][4], cM1[2][4][4];
    ZEROC(cM0, 2, 4); ZEROC(cM1, 2, 4);
    for (int ht = 0; ht < 8; ht++){
        float cH[2][4][4];
        ZEROC(cH, 2, 4);
        gemm_h(aLaneA, LDAh, g_W1H + (size_t)ht*128*DIMC, DIMC, 0, 4, sB_u, bLane, cH, tid);
        #pragma unroll
        for (int mf = 0; mf < 2; mf++)
        #pragma unroll
        for (int nf = 0; nf < 4; nf++)
        #pragma unroll
        for (int hh = 0; hh < 2; hh++){
            int r = wm + mf*16 + g + hh*8;
            int col = wn*32 + nf*8 + 2*t;
            float h0 = fmaxf(cH[mf][nf][2*hh+0] + b1[ht*128 + col],     0.f);
            float h1 = fmaxf(cH[mf][nf][2*hh+1] + b1[ht*128 + col + 1], 0.f);
            *(__half2*)(sHh + r*LDHh + col) = __floats2half2_rn(h0, h1);
        }
        gemm_h(aLaneH, LDHh, g_W2H,                   HID, ht*128, 2, sB_u, bLane, cM0, tid);
        gemm_h(aLaneH, LDHh, g_W2H + (size_t)128*HID, HID, ht*128, 2, sB_u, bLane, cM1, tid);
    }

    // ---- LN6 -> yout ----
    {
        float ps[2][2] = {}, pq[2][2] = {};
        #pragma unroll
        for (int nc = 0; nc < 2; nc++)
        #pragma unroll
        for (int mf = 0; mf < 2; mf++)
        #pragma unroll
        for (int nf = 0; nf < 4; nf++)
        #pragma unroll
        for (int hh = 0; hh < 2; hh++){
            float* cc = nc ? cM1[mf][nf] : cM0[mf][nf];
            int r = wm + mf*16 + g + hh*8;
            int col = nc*128 + wn*32 + nf*8 + 2*t;
            float2 hi = __half22float2(*(__half2*)(sAh + r*LDAh + col));
            float2 lo = __half22float2(*(__half2*)(sRh + r*LDAh + col));
            float v0 = cc[2*hh+0] + b2[col]   + hi.x + lo.x;
            float v1 = cc[2*hh+1] + b2[col+1] + hi.y + lo.y;
            cc[2*hh+0] = v0; cc[2*hh+1] = v1;
            ps[mf][hh] += v0 + v1; pq[mf][hh] += v0*v0 + v1*v1;
        }
        #pragma unroll
        for (int mf = 0; mf < 2; mf++)
        #pragma unroll
        for (int hh = 0; hh < 2; hh++){
            ps[mf][hh] += __shfl_xor_sync(~0u, ps[mf][hh], 1);
            ps[mf][hh] += __shfl_xor_sync(~0u, ps[mf][hh], 2);
            pq[mf][hh] += __shfl_xor_sync(~0u, pq[mf][hh], 1);
            pq[mf][hh] += __shfl_xor_sync(~0u, pq[mf][hh], 2);
        }
        __syncthreads();
        if (t == 0){
            #pragma unroll
            for (int mf = 0; mf < 2; mf++)
            #pragma unroll
            for (int hh = 0; hh < 2; hh++){
                int r = wm + mf*16 + g + hh*8;
                sS [wn*128 + r] = ps[mf][hh];
                sAg[wn*128 + r] = pq[mf][hh];
            }
        }
        __syncthreads();
        float* youtb = yout + (size_t)bi*NTOK*DIMC;
        #pragma unroll
        for (int mf = 0; mf < 2; mf++)
        #pragma unroll
        for (int hh = 0; hh < 2; hh++){
            int r = wm + mf*16 + g + hh*8;
            float S = sS[r] + sS[128+r] + sS[256+r] + sS[384+r];
            float Q = sAg[r] + sAg[128+r] + sAg[256+r] + sAg[384+r];
            float mean = S * (1.f/256.f);
            float rstd = rsqrtf(Q*(1.f/256.f) - mean*mean + EPSV);
            #pragma unroll
            for (int nc = 0; nc < 2; nc++)
            #pragma unroll
            for (int nf = 0; nf < 4; nf++){
                float* cc = nc ? cM1[mf][nf] : cM0[mf][nf];
                int col = nc*128 + wn*32 + nf*8 + 2*t;
                float v0 = (cc[2*hh+0] - mean)*rstd*ln6s[col]   + ln6b[col];
                float v1 = (cc[2*hh+1] - mean)*rstd*ln6s[col+1] + ln6b[col+1];
                *(float2*)(youtb + (size_t)r*DIMC + col) = make_float2(v0, v1);
            }
        }
    }
}

// ================= kernel 3: node post (fp16 mma, 8 rows/CTA) =================
__global__ __launch_bounds__(256) void node_post_kernel(
    const float* __restrict__ bon,
    const float* __restrict__ b1, const float* __restrict__ b2,
    const float* __restrict__ ln3s, const float* __restrict__ ln3b,
    const float* __restrict__ ln5s, const float* __restrict__ ln5b,
    float* __restrict__ xout)
{
    __shared__ __align__(16) __half sA[16*LDAh];
    __shared__ __align__(16) __half sH[16*LDHh];
    __shared__ float  sX[8*260];
    __shared__ float  sRed[2][64];

    int tid = threadIdx.x, lane = tid & 31, w = tid >> 5;
    int r0 = blockIdx.x * 8;
    int sub = lane >> 3, rin = lane & 7;
    int g = lane >> 2, t2 = (lane & 3)*2;

    for (int i = tid; i < 8*256; i += 256){
        int r = i >> 8, c = i & 255;
        sA[r*LDAh + c] = __float2half_rn(g_agg[(size_t)(r0+r)*DIMC + c]);
    }
    for (int i = tid; i < 8*LDAh; i += 256) sA[8*LDAh + i] = __float2half_rn(0.f);
    for (int i = tid; i < 8*LDHh; i += 256) sH[8*LDHh + i] = __float2half_rn(0.f);
    __syncthreads();

    uint32_t aLane = (uint32_t)__cvta_generic_to_shared(sA)
                   + (uint32_t)((((sub&1)*8 + rin)*LDAh + (sub>>1)*8)*2);
    uint32_t hLane = (uint32_t)__cvta_generic_to_shared(sH)
                   + (uint32_t)((((sub&1)*8 + rin)*LDHh + (sub>>1)*8)*2);

    // GEMM: x2pre = agg @ Won
    float c1[4][4];
    #pragma unroll
    for (int nf = 0; nf < 4; nf++)
        #pragma unroll
        for (int u = 0; u < 4; u++) c1[nf][u] = 0.f;
    {
        const __half* base = g_WonH + (size_t)(w*32 + (lane>>2))*DIMC + (lane&3)*2;
        #pragma unroll
        for (int kk = 0; kk < 16; kk++){
            uint32_t a[4];
            ldsm4(a, aLane + (uint32_t)(kk*16*2));
            #pragma unroll
            for (int nf = 0; nf < 4; nf++){
                const __half* bp = base + (size_t)nf*8*DIMC + kk*16;
                uint32_t b[2] = { *(const uint32_t*)bp, *(const uint32_t*)(bp + 8) };
                mma16(c1[nf], a, b);
            }
        }
    }
    // epilogue + LN3
    {
        float v[4][2], ps = 0.f, pq = 0.f;
        #pragma unroll
        for (int nf = 0; nf < 4; nf++){
            int col = w*32 + nf*8 + t2;
            float2 x1v = *(const float2*)(g_x1 + (size_t)(r0+g)*DIMC + col);
            v[nf][0] = c1[nf][0] + bon[col]   + x1v.x;
            v[nf][1] = c1[nf][1] + bon[col+1] + x1v.y;
            ps += v[nf][0] + v[nf][1];
            pq += v[nf][0]*v[nf][0] + v[nf][1]*v[nf][1];
        }
        ps += __shfl_xor_sync(~0u, ps, 1); pq += __shfl_xor_sync(~0u, pq, 1);
        ps += __shfl_xor_sync(~0u, ps, 2); pq += __shfl_xor_sync(~0u, pq, 2);
        if ((lane & 3) == 0){ sRed[0][w*8 + g] = ps; sRed[1][w*8 + g] = pq; }
        __syncthreads();
        float S = 0.f, Q = 0.f;
        #pragma unroll
        for (int ww = 0; ww < 8; ww++){ S += sRed[0][ww*8 + g]; Q += sRed[1][ww*8 + g]; }
        float mean = S * (1.f/256.f);
        float rstd = rsqrtf(Q*(1.f/256.f) - mean*mean + EPSV);
        #pragma unroll
        for (int nf = 0; nf < 4; nf++){
            int col = w*32 + nf*8 + t2;
            float x0 = (v[nf][0] - mean)*rstd*ln3s[col]   + ln3b[col];
            float x1 = (v[nf][1] - mean)*rstd*ln3s[col+1] + ln3b[col+1];
            sX[g*260 + col] = x0; sX[g*260 + col + 1] = x1;
            *(__half2*)(sA + g*LDAh + col) = __floats2half2_rn(x0, x1);
        }
        __syncthreads();
    }

    // MLP: ht-interleaved (NODE weights g_N1H/g_N2H)
    float cM[4][4];
    #pragma unroll
    for (int nf = 0; nf < 4; nf++)
        #pragma unroll
        for (int u = 0; u < 4; u++) cM[nf][u] = 0.f;
    for (int ht = 0; ht < 8; ht++){
        float cH[2][4];
        #pragma unroll
        for (int nf = 0; nf < 2; nf++)
            #pragma unroll
            for (int u = 0; u < 4; u++) cH[nf][u] = 0.f;
        {
            const __half* base = g_N1H + (size_t)(ht*128 + w*16 + (lane>>2))*DIMC + (lane&3)*2;
            #pragma unroll
            for (int kk = 0; kk < 16; kk++){
                uint32_t a[4];
                ldsm4(a, aLane + (uint32_t)(kk*16*2));
                #pragma unroll
                for (int nf = 0; nf < 2; nf++){
                    const __half* bp = base + (size_t)nf*8*DIMC + kk*16;
                    uint32_t b[2] = { *(const uint32_t*)bp, *(const uint32_t*)(bp + 8) };
                    mma16(cH[nf], a, b);
                }
            }
        }
        __syncthreads();   // prev GEMM4 reads of sH done
        #pragma unroll
        for (int nf = 0; nf < 2; nf++){
            int col = w*16 + nf*8 + t2;
            float h0 = fmaxf(cH[nf][0] + b1[ht*128 + col],     0.f);
            float h1 = fmaxf(cH[nf][1] + b1[ht*128 + col + 1], 0.f);
            *(__half2*)(sH + g*LDHh + col) = __floats2half2_rn(h0, h1);
        }
        __syncthreads();
        {
            const __half* base = g_N2H + (size_t)(w*32 + (lane>>2))*HID + ht*128 + (lane&3)*2;
            #pragma unroll
            for (int kk = 0; kk < 8; kk++){
                uint32_t a[4];
                ldsm4(a, hLane + (uint32_t)(kk*16*2));
                #pragma unroll
                for (int nf = 0; nf < 4; nf++){
                    const __half* bp = base + (size_t)nf*8*HID + kk*16;
                    uint32_t b[2] = { *(const uint32_t*)bp, *(const uint32_t*)(bp + 8) };
                    mma16(cM[nf], a, b);
                }
            }
        }
    }

    // final: out = cM + b2 + x2 ; LN5 -> xout
    {
        float v[4][2], ps = 0.f, pq = 0.f;
        #pragma unroll
        for (int nf = 0; nf < 4; nf++){
            int col = w*32 + nf*8 + t2;
            v[nf][0] = cM[nf][0] + b2[col]   + sX[g*260 + col];
            v[nf][1] = cM[nf][1] + b2[col+1] + sX[g*260 + col + 1];
            ps += v[nf][0] + v[nf][1];
            pq += v[nf][0]*v[nf][0] + v[nf][1]*v[nf][1];
        }
        ps += __shfl_xor_sync(~0u, ps, 1); pq += __shfl_xor_sync(~0u, pq, 1);
        ps += __shfl_xor_sync(~0u, ps, 2); pq += __shfl_xor_sync(~0u, pq, 2);
        __syncthreads();
        if ((lane & 3) == 0){ sRed[0][w*8 + g] = ps; sRed[1][w*8 + g] = pq; }
        __syncthreads();
        float S = 0.f, Q = 0.f;
        #pragma unroll
        for (int ww = 0; ww < 8; ww++){ S += sRed[0][ww*8 + g]; Q += sRed[1][ww*8 + g]; }
        float mean = S * (1.f/256.f);
        float rstd = rsqrtf(Q*(1.f/256.f) - mean*mean + EPSV);
        #pragma unroll
        for (int nf = 0; nf < 4; nf++){
            int col = w*32 + nf*8 + t2;
            float o0 = (v[nf][0] - mean)*rstd*ln5s[col]   + ln5b[col];
            float o1 = (v[nf][1] - mean)*rstd*ln5s[col+1] + ln5b[col+1];
            *(float2*)(xout + (size_t)(r0+g)*DIMC + col) = make_float2(o0, o1);
        }
    }
}

// ================= launch =================
extern "C" void kernel_launch(void* const* d_in, const int* in_sizes, int n_in,
                              void* d_out, int out_size)
{
    const float* x    = (const float*)d_in[0];
    const float* y    = (const float*)d_in[1];
    const float* Wq   = (const float*)d_in[2];  const float* bq  = (const float*)d_in[3];
    const float* Wk   = (const float*)d_in[4];  const float* bk  = (const float*)d_in[5];
    const float* Wv   = (const float*)d_in[6];  const float* bv  = (const float*)d_in[7];
    const float* We   = (const float*)d_in[8];  const float* be  = (const float*)d_in[9];
    const float* Woe  = (const float*)d_in[10]; const float* boe = (const float*)d_in[11];
    const float* Won  = (const float*)d_in[12]; const float* bon = (const float*)d_in[13];
    const float* m1w1 = (const float*)d_in[14]; const float* m1b1= (const float*)d_in[15];
    const float* m1w2 = (const float*)d_in[16]; const float* m1b2= (const float*)d_in[17];
    const float* m2w1 = (const float*)d_in[18]; const float* m2b1= (const float*)d_in[19];
    const float* m2w2 = (const float*)d_in[20]; const float* m2b2= (const float*)d_in[21];
    const float* ln1s = (const float*)d_in[22]; const float* ln1b= (const float*)d_in[23];
    const float* ln3s = (const float*)d_in[24]; const float* ln3b= (const float*)d_in[25];
    const float* ln4s = (const float*)d_in[26]; const float* ln4b= (const float*)d_in[27];
    const float* ln5s = (const float*)d_in[28]; const float* ln5b= (const float*)d_in[29];
    const float* ln6s = (const float*)d_in[30]; const float* ln6b= (const float*)d_in[31];

    float* out  = (float*)d_out;
    float* xout = out;                               // (8,128,256)
    float* yout = out + BAT*NTOK*DIMC;               // (8,128,128,256)

    int smem = 211968;
    cudaFuncSetAttribute(edge_kernel, cudaFuncAttributeMaxDynamicSharedMemorySize, smem);

    prep_kernel<<<1024, 256>>>(We, Woe, m2w1, m2w2, m1w1, m1w2, Won, Wq, Wk, Wv);
    node_pre_kernel<<<BAT*NTOK/8, 256>>>(x, bq, bk, bv, ln1s, ln1b);
    edge_kernel<<<BAT*NTOK, 512, smem>>>(y, be, boe, m2b1, m2b2,
                                         ln4s, ln4b, ln6s, ln6b, yout);
    node_post_kernel<<<BAT*NTOK/8, 256>>>(bon, m1b1, m1b2,
                                          ln3s, ln3b, ln5s, ln5b, xout);
}